// round 2
// baseline (speedup 1.0000x reference)
#include <cuda_runtime.h>

typedef unsigned long long u64;
#define DI __device__ __forceinline__

constexpr int B=2, L=32512, R=64, S=128, NM=80, NC=256, NB=30, MD=10;
constexpr int KRED=208, TT=128, NTILE=L/TT; // 254

__device__ __align__(16) float g_cond[B*NM*L];
__device__ __align__(16) float g_res[2][B*R*L];
__device__ __align__(16) float g_skip[B*S*L];
__device__ __align__(16) float g_Wz[NB*KRED*128];
__device__ __align__(16) float g_W2[NB*64*192];
__device__ __align__(16) float g_bz[NB*128];
__device__ __align__(16) float g_Wp1[128*256];
__device__ __align__(16) float g_Wp2[256*256];

DI u64 dup2(float v){u64 r;asm("mov.b64 %0,{%1,%1};":"=l"(r):"f"(v));return r;}
DI void ffma2(u64&d,u64 a,u64 b){asm("fma.rn.f32x2 %0,%1,%2,%0;":"+l"(d):"l"(a),"l"(b));}
DI float2 unpack2(u64 v){float x,y;asm("mov.b64 {%0,%1},%2;":"=f"(x),"=f"(y):"l"(v));return make_float2(x,y);}
#define FMA4(AC,WS){u64 ww_=dup2(WS);ffma2((AC)[0],ww_,A0.x);ffma2((AC)[1],ww_,A0.y);ffma2((AC)[2],ww_,A1.x);ffma2((AC)[3],ww_,A1.y);}

__global__ void prep_kernel(const float* __restrict__ dw,const float* __restrict__ db,
    const float* __restrict__ cw,const float* __restrict__ cb,
    const float* __restrict__ sw,const float* __restrict__ rw,
    const float* __restrict__ p1w,const float* __restrict__ p2w){
  const int N0=NB*KRED*128,N1=NB*64*192,N2=NB*128,N3=128*256,N4=256*256;
  const int total=N0+N1+N2+N3+N4;
  for(int idx=blockIdx.x*blockDim.x+threadIdx.x;idx<total;idx+=gridDim.x*blockDim.x){
    int t=idx;
    if(t<N0){int i=t/(KRED*128);int rem=t%(KRED*128);int j=rem>>7;int co=rem&127;float v;
      if(j<64)v=dw[(((i*128+co)*64)+j)*2+1];
      else if(j<128)v=dw[(((i*128+co)*64)+(j-64))*2+0];
      else v=cw[(i*128+co)*80+(j-128)];
      g_Wz[t]=v;continue;}
    t-=N0;
    if(t<N1){int i=t/(64*192);int rem=t%(64*192);int ci=rem/192;int co=rem%192;
      g_W2[t]=(co<128)?sw[(i*128+co)*64+ci]:rw[(i*64+(co-128))*64+ci];continue;}
    t-=N1;
    if(t<N2){g_bz[t]=db[t]+cb[t];continue;}
    t-=N2;
    if(t<N3){int ci=t>>8;int co=t&255;g_Wp1[t]=p1w[co*128+ci];continue;}
    t-=N3;
    {int ci=t>>8;int co=t&255;g_Wp2[t]=p2w[co*256+ci];}
  }
}

__global__ void cond_kernel(const float* __restrict__ mels,const float* __restrict__ mw,
    const float* __restrict__ mb){
  extern __shared__ float sm[];
  float* melS=sm;               // [B][NM][128]
  float* wS=sm+B*NM*128;        // [160][80]
  const int tid=threadIdx.x;const int r=blockIdx.x;
  for(int k=tid;k<(B*NM*128)/4;k+=256)((float4*)melS)[k]=((const float4*)mels)[k];
  const int k1=255-r,k2=511-r;
  for(int idx=tid;idx<160*80;idx+=256){int j=idx/80,c=idx%80;
    int m=(j<80)?j:(j-80);int k=(j<80)?k1:k2;
    wS[idx]=mw[(c*NM+m)*512+k];}
  __syncthreads();
  for(int idx=tid;idx<B*NM*127;idx+=256){
    int q=idx%127;int c=(idx/127)%NM;int b=idx/(127*NM);
    float acc=mb[c];
    const float* m0=melS+b*NM*128+q;
    #pragma unroll 4
    for(int m=0;m<NM;m++){
      acc+=wS[m*80+c]*m0[m*128]+wS[(80+m)*80+c]*m0[m*128+1];}
    g_cond[(b*NM+c)*L+q*256+r]=acc;
  }
}

__global__ void init_res_kernel(const float* __restrict__ x,const float* __restrict__ iw,
    const float* __restrict__ ib){
  int idx=blockIdx.x*blockDim.x+threadIdx.x;
  if(idx>=B*R*L)return;
  int t=idx%L;int rc=(idx/L)%R;int b=idx/(L*R);
  g_res[0][idx]=iw[rc]*x[b*L+t]+ib[rc];
}

__global__ void __launch_bounds__(256,1) block_kernel(int blk,int d,int pp,int first,
    const float* __restrict__ skip_b,const float* __restrict__ res_b){
  extern __shared__ float sm[];
  float* actT=sm;            // [208][128]
  float* hS=sm+KRED*TT;      // [64][128]
  float* wb=hS+64*TT;        // [16][192]
  const int tid=threadIdx.x;
  const int a=tid>>4,bb=tid&15;
  const int a4=a*4,a8=a*8,b4=bb*4;
  const int bIdx=blockIdx.y;const int t0=blockIdx.x*TT;
  const float* res_in=g_res[pp]+bIdx*(R*L);
  float* res_out=g_res[pp^1]+bIdx*(R*L);
  const float* condp=g_cond+bIdx*(NM*L);

  for(int k=tid;k<R*(TT/4);k+=256){int ci=k>>5,c4=k&31;
    ((float4*)(actT+ci*TT))[c4]=((const float4*)(res_in+ci*L+t0))[c4];}
  for(int k=tid;k<R*TT;k+=256){int ci=k>>7,c=k&(TT-1);
    int tg=t0+c-d;
    actT[(R+ci)*TT+c]=(tg>=0)?res_in[ci*L+tg]:0.0f;}
  for(int k=tid;k<NM*(TT/4);k+=256){int ci=k>>5,c4=k&31;
    ((float4*)(actT+(2*R+ci)*TT))[c4]=((const float4*)(condp+ci*L+t0))[c4];}

  u64 accF[4][4],accG[4][4];
  #pragma unroll
  for(int j=0;j<4;j++)
    #pragma unroll
    for(int p=0;p<4;p++){accF[j][p]=0ull;accG[j][p]=0ull;}
  const float* Wz=g_Wz+blk*(KRED*128);
  for(int ch=0;ch<KRED;ch+=16){
    __syncthreads();
    const float4* wsrc=(const float4*)(Wz+ch*128);
    ((float4*)wb)[tid]=wsrc[tid];
    ((float4*)wb)[tid+256]=wsrc[tid+256];
    __syncthreads();
    #pragma unroll
    for(int ci=0;ci<16;ci++){
      const float* wrow=wb+ci*128;
      float4 wf=*(const float4*)(wrow+a4);
      float4 wg=*(const float4*)(wrow+64+a4);
      const float* arow=actT+(ch+ci)*TT;
      ulonglong2 A0=*(const ulonglong2*)(arow+b4);
      ulonglong2 A1=*(const ulonglong2*)(arow+64+b4);
      FMA4(accF[0],wf.x);FMA4(accF[1],wf.y);FMA4(accF[2],wf.z);FMA4(accF[3],wf.w);
      FMA4(accG[0],wg.x);FMA4(accG[1],wg.y);FMA4(accG[2],wg.z);FMA4(accG[3],wg.w);
    }
  }

  const float* bz=g_bz+blk*128;
  #pragma unroll
  for(int j=0;j<4;j++){
    float bf=bz[a4+j],bg=bz[64+a4+j];
    #pragma unroll
    for(int qp=0;qp<4;qp++){
      float2 f=unpack2(accF[j][qp]);float2 g=unpack2(accG[j][qp]);
      f.x+=bf;f.y+=bf;g.x+=bg;g.y+=bg;
      float2 h;
      h.x=tanhf(f.x)*(1.0f/(1.0f+__expf(-g.x)));
      h.y=tanhf(f.y)*(1.0f/(1.0f+__expf(-g.y)));
      int col=(qp>>1)*64+b4+(qp&1)*2;
      *(float2*)(hS+(a4+j)*TT+col)=h;
    }
  }

  u64 accS[8][4],accR[4][4];
  #pragma unroll
  for(int j=0;j<8;j++)
    #pragma unroll
    for(int p=0;p<4;p++)accS[j][p]=0ull;
  #pragma unroll
  for(int j=0;j<4;j++)
    #pragma unroll
    for(int p=0;p<4;p++)accR[j][p]=0ull;
  const float* W2=g_W2+blk*(64*192);
  for(int ch=0;ch<64;ch+=16){
    __syncthreads();
    const float4* wsrc=(const float4*)(W2+ch*192);
    ((float4*)wb)[tid]=wsrc[tid];
    ((float4*)wb)[tid+256]=wsrc[tid+256];
    ((float4*)wb)[tid+512]=wsrc[tid+512];
    __syncthreads();
    #pragma unroll
    for(int ci=0;ci<16;ci++){
      const float* wrow=wb+ci*192;
      float4 w0=*(const float4*)(wrow+a8);
      float4 w1=*(const float4*)(wrow+a8+4);
      float4 wr=*(const float4*)(wrow+128+a4);
      const float* arow=hS+(ch+ci)*TT;
      ulonglong2 A0=*(const ulonglong2*)(arow+b4);
      ulonglong2 A1=*(const ulonglong2*)(arow+64+b4);
      FMA4(accS[0],w0.x);FMA4(accS[1],w0.y);FMA4(accS[2],w0.z);FMA4(accS[3],w0.w);
      FMA4(accS[4],w1.x);FMA4(accS[5],w1.y);FMA4(accS[6],w1.z);FMA4(accS[7],w1.w);
      FMA4(accR[0],wr.x);FMA4(accR[1],wr.y);FMA4(accR[2],wr.z);FMA4(accR[3],wr.w);
    }
  }

  float* skipp=g_skip+bIdx*(S*L);
  #pragma unroll
  for(int j=0;j<8;j++){
    int co=a8+j;float sb=skip_b[blk*S+co];
    #pragma unroll
    for(int q=0;q<2;q++){
      float2 v0=unpack2(accS[j][q*2+0]);float2 v1=unpack2(accS[j][q*2+1]);
      float4 v=make_float4(v0.x+sb,v0.y+sb,v1.x+sb,v1.y+sb);
      float4* dst=(float4*)(skipp+co*L+t0+q*64+b4);
      if(!first){float4 o=*dst;v.x+=o.x;v.y+=o.y;v.z+=o.z;v.w+=o.w;}
      *dst=v;
    }
  }
  #pragma unroll
  for(int j=0;j<4;j++){
    int co=a4+j;float rb=res_b[blk*R+co];
    #pragma unroll
    for(int q=0;q<2;q++){
      float2 v0=unpack2(accR[j][q*2+0]);float2 v1=unpack2(accR[j][q*2+1]);
      float4 cur=*(const float4*)(actT+co*TT+q*64+b4);
      float4 v=make_float4(cur.x+v0.x+rb,cur.y+v0.y+rb,cur.z+v1.x+rb,cur.w+v1.y+rb);
      *(float4*)(res_out+co*L+t0+q*64+b4)=v;
    }
  }
}

__global__ void __launch_bounds__(256,1) post_kernel(const float* __restrict__ p1b,
    const float* __restrict__ p2b,float* __restrict__ out){
  extern __shared__ float sm[];
  float* xS=sm;             // [128][128]
  float* y1S=sm+S*TT;       // [256][128]
  float* wb=y1S+NC*TT;      // [16][256]
  const int tid=threadIdx.x;
  const int a=tid>>4,bb=tid&15;
  const int a8=a*8,b4=bb*4;
  const int bIdx=blockIdx.y;const int t0=blockIdx.x*TT;

  for(int k=tid;k<S*(TT/4);k+=256){int ci=k>>5,c4=k&31;
    float4 v=((const float4*)(g_skip+(bIdx*S+ci)*L+t0))[c4];
    v.x=fmaxf(v.x,0.f);v.y=fmaxf(v.y,0.f);v.z=fmaxf(v.z,0.f);v.w=fmaxf(v.w,0.f);
    ((float4*)(xS+ci*TT))[c4]=v;}

  u64 acc0[8][4],acc1[8][4];
  #pragma unroll
  for(int j=0;j<8;j++)
    #pragma unroll
    for(int p=0;p<4;p++){acc0[j][p]=0ull;acc1[j][p]=0ull;}
  for(int ch=0;ch<S;ch+=16){
    __syncthreads();
    const float4* wsrc=(const float4*)(g_Wp1+ch*256);
    ((float4*)wb)[tid]=wsrc[tid];((float4*)wb)[tid+256]=wsrc[tid+256];
    ((float4*)wb)[tid+512]=wsrc[tid+512];((float4*)wb)[tid+768]=wsrc[tid+768];
    __syncthreads();
    #pragma unroll
    for(int ci=0;ci<16;ci++){
      const float* wrow=wb+ci*256;
      float4 wa0=*(const float4*)(wrow+a8);float4 wa1=*(const float4*)(wrow+a8+4);
      float4 wb0=*(const float4*)(wrow+128+a8);float4 wb1=*(const float4*)(wrow+128+a8+4);
      const float* arow=xS+(ch+ci)*TT;
      ulonglong2 A0=*(const ulonglong2*)(arow+b4);
      ulonglong2 A1=*(const ulonglong2*)(arow+64+b4);
      FMA4(acc0[0],wa0.x);FMA4(acc0[1],wa0.y);FMA4(acc0[2],wa0.z);FMA4(acc0[3],wa0.w);
      FMA4(acc0[4],wa1.x);FMA4(acc0[5],wa1.y);FMA4(acc0[6],wa1.z);FMA4(acc0[7],wa1.w);
      FMA4(acc1[0],wb0.x);FMA4(acc1[1],wb0.y);FMA4(acc1[2],wb0.z);FMA4(acc1[3],wb0.w);
      FMA4(acc1[4],wb1.x);FMA4(acc1[5],wb1.y);FMA4(acc1[6],wb1.z);FMA4(acc1[7],wb1.w);
    }
  }
  #pragma unroll
  for(int j=0;j<8;j++){
    int co0=a8+j,co1=128+a8+j;
    float bb0=p1b[co0],bb1=p1b[co1];
    #pragma unroll
    for(int q=0;q<2;q++){
      float2 u0=unpack2(acc0[j][q*2]);float2 u1=unpack2(acc0[j][q*2+1]);
      *(float4*)(y1S+co0*TT+q*64+b4)=make_float4(fmaxf(u0.x+bb0,0.f),fmaxf(u0.y+bb0,0.f),fmaxf(u1.x+bb0,0.f),fmaxf(u1.y+bb0,0.f));
      float2 s0=unpack2(acc1[j][q*2]);float2 s1=unpack2(acc1[j][q*2+1]);
      *(float4*)(y1S+co1*TT+q*64+b4)=make_float4(fmaxf(s0.x+bb1,0.f),fmaxf(s0.y+bb1,0.f),fmaxf(s1.x+bb1,0.f),fmaxf(s1.y+bb1,0.f));
    }
  }

  #pragma unroll
  for(int j=0;j<8;j++)
    #pragma unroll
    for(int p=0;p<4;p++){acc0[j][p]=0ull;acc1[j][p]=0ull;}
  for(int ch=0;ch<NC;ch+=16){
    __syncthreads();
    const float4* wsrc=(const float4*)(g_Wp2+ch*256);
    ((float4*)wb)[tid]=wsrc[tid];((float4*)wb)[tid+256]=wsrc[tid+256];
    ((float4*)wb)[tid+512]=wsrc[tid+512];((float4*)wb)[tid+768]=wsrc[tid+768];
    __syncthreads();
    #pragma unroll
    for(int ci=0;ci<16;ci++){
      const float* wrow=wb+ci*256;
      float4 wa0=*(const float4*)(wrow+a8);float4 wa1=*(const float4*)(wrow+a8+4);
      float4 wb0=*(const float4*)(wrow+128+a8);float4 wb1=*(const float4*)(wrow+128+a8+4);
      const float* arow=y1S+(ch+ci)*TT;
      ulonglong2 A0=*(const ulonglong2*)(arow+b4);
      ulonglong2 A1=*(const ulonglong2*)(arow+64+b4);
      FMA4(acc0[0],wa0.x);FMA4(acc0[1],wa0.y);FMA4(acc0[2],wa0.z);FMA4(acc0[3],wa0.w);
      FMA4(acc0[4],wa1.x);FMA4(acc0[5],wa1.y);FMA4(acc0[6],wa1.z);FMA4(acc0[7],wa1.w);
      FMA4(acc1[0],wb0.x);FMA4(acc1[1],wb0.y);FMA4(acc1[2],wb0.z);FMA4(acc1[3],wb0.w);
      FMA4(acc1[4],wb1.x);FMA4(acc1[5],wb1.y);FMA4(acc1[6],wb1.z);FMA4(acc1[7],wb1.w);
    }
  }
  #pragma unroll
  for(int j=0;j<8;j++){
    int co0=a8+j,co1=128+a8+j;
    float bb0=p2b[co0],bb1=p2b[co1];
    #pragma unroll
    for(int q=0;q<2;q++){
      float2 u0=unpack2(acc0[j][q*2]);float2 u1=unpack2(acc0[j][q*2+1]);
      *(float4*)(out+(bIdx*NC+co0)*L+t0+q*64+b4)=make_float4(u0.x+bb0,u0.y+bb0,u1.x+bb0,u1.y+bb0);
      float2 s0=unpack2(acc1[j][q*2]);float2 s1=unpack2(acc1[j][q*2+1]);
      *(float4*)(out+(bIdx*NC+co1)*L+t0+q*64+b4)=make_float4(s0.x+bb1,s0.y+bb1,s1.x+bb1,s1.y+bb1);
    }
  }
}

extern "C" void kernel_launch(void* const* d_in, const int* in_sizes, int n_in,
                              void* d_out, int out_size) {
  const float* x      =(const float*)d_in[0];
  const float* mels   =(const float*)d_in[1];
  const float* input_w=(const float*)d_in[2];
  const float* input_b=(const float*)d_in[3];
  const float* mel_w  =(const float*)d_in[4];
  const float* mel_b  =(const float*)d_in[5];
  const float* dil_w  =(const float*)d_in[6];
  const float* dil_b  =(const float*)d_in[7];
  const float* cond_w =(const float*)d_in[8];
  const float* cond_b =(const float*)d_in[9];
  const float* skip_w =(const float*)d_in[10];
  const float* skip_b =(const float*)d_in[11];
  const float* res_w  =(const float*)d_in[12];
  const float* res_b  =(const float*)d_in[13];
  const float* p1w    =(const float*)d_in[14];
  const float* p1b    =(const float*)d_in[15];
  const float* p2w    =(const float*)d_in[16];
  const float* p2b    =(const float*)d_in[17];
  float* out=(float*)d_out;

  const int condSmem=(B*NM*128+160*80)*4;          // 133120
  const int blkSmem=(KRED*TT+64*TT+16*192)*4;      // 151552
  const int postSmem=(S*TT+NC*TT+16*256)*4;        // 212992
  cudaFuncSetAttribute(cond_kernel, cudaFuncAttributeMaxDynamicSharedMemorySize, condSmem);
  cudaFuncSetAttribute(block_kernel, cudaFuncAttributeMaxDynamicSharedMemorySize, blkSmem);
  cudaFuncSetAttribute(post_kernel, cudaFuncAttributeMaxDynamicSharedMemorySize, postSmem);

  prep_kernel<<<1024,256>>>(dil_w,dil_b,cond_w,cond_b,skip_w,res_w,p1w,p2w);
  cond_kernel<<<256,256,condSmem>>>(mels,mel_w,mel_b);
  init_res_kernel<<<(B*R*L+255)/256,256>>>(x,input_w,input_b);
  for(int i=0;i<NB;i++){
    int d=1<<(i%MD);
    block_kernel<<<dim3(NTILE,B),256,blkSmem>>>(i,d,i&1,i==0?1:0,skip_b,res_b);
  }
  post_kernel<<<dim3(NTILE,B),256,postSmem>>>(p1b,p2b,out);
}

// round 4
// speedup vs baseline: 1.0292x; 1.0292x over previous
#include <cuda_runtime.h>

typedef unsigned long long u64;
#define DI __device__ __forceinline__

constexpr int B=2, L=32512, R=64, S=128, NM=80, NC=256, NB=30, MD=10;
constexpr int KRED=208, TT=128, NTILE=L/TT; // 254

__device__ __align__(16) float g_cond[B*NM*L];
__device__ __align__(16) float g_res[2][B*R*L];
__device__ __align__(16) float g_skip[B*S*L];
__device__ __align__(16) float g_Wz[NB*KRED*128];
__device__ __align__(16) float g_W2[NB*64*192];
__device__ __align__(16) float g_bz[NB*128];
__device__ __align__(16) float g_Wp1[128*256];
__device__ __align__(16) float g_Wp2[256*256];

DI u64 dup2(float v){u64 r;asm("mov.b64 %0,{%1,%1};":"=l"(r):"f"(v));return r;}
DI void ffma2(u64&d,u64 a,u64 b){asm("fma.rn.f32x2 %0,%1,%2,%0;":"+l"(d):"l"(a),"l"(b));}
DI float2 unpack2(u64 v){float x,y;asm("mov.b64 {%0,%1},%2;":"=f"(x),"=f"(y):"l"(v));return make_float2(x,y);}
#define FMA4(AC,WS){u64 ww_=dup2(WS);ffma2((AC)[0],ww_,A0.x);ffma2((AC)[1],ww_,A0.y);ffma2((AC)[2],ww_,A1.x);ffma2((AC)[3],ww_,A1.y);}

__global__ void prep_kernel(const float* __restrict__ dw,const float* __restrict__ db,
    const float* __restrict__ cw,const float* __restrict__ cb,
    const float* __restrict__ sw,const float* __restrict__ rw,
    const float* __restrict__ p1w,const float* __restrict__ p2w){
  const int N0=NB*KRED*128,N1=NB*64*192,N2=NB*128,N3=128*256,N4=256*256;
  const int total=N0+N1+N2+N3+N4;
  for(int idx=blockIdx.x*blockDim.x+threadIdx.x;idx<total;idx+=gridDim.x*blockDim.x){
    int t=idx;
    if(t<N0){int i=t/(KRED*128);int rem=t%(KRED*128);int j=rem>>7;int co=rem&127;float v;
      if(j<64)v=dw[(((i*128+co)*64)+j)*2+1];
      else if(j<128)v=dw[(((i*128+co)*64)+(j-64))*2+0];
      else v=cw[(i*128+co)*80+(j-128)];
      g_Wz[t]=v;continue;}
    t-=N0;
    if(t<N1){int i=t/(64*192);int rem=t%(64*192);int ci=rem/192;int co=rem%192;
      g_W2[t]=(co<128)?sw[(i*128+co)*64+ci]:rw[(i*64+(co-128))*64+ci];continue;}
    t-=N1;
    if(t<N2){g_bz[t]=db[t]+cb[t];continue;}
    t-=N2;
    if(t<N3){int ci=t>>8;int co=t&255;g_Wp1[t]=p1w[co*128+ci];continue;}
    t-=N3;
    {int ci=t>>8;int co=t&255;g_Wp2[t]=p2w[co*256+ci];}
  }
}

__global__ void cond_kernel(const float* __restrict__ mels,const float* __restrict__ mw,
    const float* __restrict__ mb){
  extern __shared__ float sm[];
  float* melS=sm;               // [B][NM][128]
  float* wS=sm+B*NM*128;        // [160][80]
  const int tid=threadIdx.x;const int r=blockIdx.x;
  for(int k=tid;k<(B*NM*128)/4;k+=256)((float4*)melS)[k]=((const float4*)mels)[k];
  const int k1=255-r,k2=511-r;
  for(int idx=tid;idx<160*80;idx+=256){int j=idx/80,c=idx%80;
    int m=(j<80)?j:(j-80);int k=(j<80)?k1:k2;
    wS[idx]=mw[(c*NM+m)*512+k];}
  __syncthreads();
  for(int idx=tid;idx<B*NM*127;idx+=256){
    int q=idx%127;int c=(idx/127)%NM;int b=idx/(127*NM);
    float acc=mb[c];
    const float* m0=melS+b*NM*128+q;
    #pragma unroll 4
    for(int m=0;m<NM;m++){
      acc+=wS[m*80+c]*m0[m*128]+wS[(80+m)*80+c]*m0[m*128+1];}
    g_cond[(b*NM+c)*L+q*256+r]=acc;
  }
}

__global__ void init_res_kernel(const float* __restrict__ x,const float* __restrict__ iw,
    const float* __restrict__ ib){
  int idx=blockIdx.x*blockDim.x+threadIdx.x;
  if(idx>=B*R*L)return;
  int t=idx%L;int rc=(idx/L)%R;int b=idx/(L*R);
  g_res[0][idx]=iw[rc]*x[b*L+t]+ib[rc];
}

// 512 threads: a in [0,32), bb in [0,16)
__global__ void __launch_bounds__(512,1) block_kernel(int blk,int d,int pp,int first,
    const float* __restrict__ skip_b,const float* __restrict__ res_b){
  extern __shared__ float sm[];
  float* actT=sm;            // [208][128]
  float* hS=sm+KRED*TT;      // [64][128]
  float* wbuf=hS+64*TT;      // [2][3072] double buffer
  const int tid=threadIdx.x;
  const int a=tid>>4,bb=tid&15;
  const int a2=a*2,a4=a*4,b4=bb*4;
  const int bIdx=blockIdx.y;const int t0=blockIdx.x*TT;
  const float* res_in=g_res[pp]+bIdx*(R*L);
  float* res_out=g_res[pp^1]+bIdx*(R*L);
  const float* condp=g_cond+bIdx*(NM*L);

  // ---- stage activations [res(t) | res(t-d) | cond] ----
  for(int k=tid;k<R*(TT/4);k+=512){int ci=k>>5,c4=k&31;
    ((float4*)(actT+ci*TT))[c4]=((const float4*)(res_in+ci*L+t0))[c4];}
  if(((d&3)==0)&&(t0>=d)){
    for(int k=tid;k<R*(TT/4);k+=512){int ci=k>>5,c4=k&31;
      ((float4*)(actT+(R+ci)*TT))[c4]=*(const float4*)(res_in+ci*L+t0-d+c4*4);}
  }else{
    for(int k=tid;k<R*TT;k+=512){int ci=k>>7,c=k&(TT-1);
      int tg=t0+c-d;
      actT[(R+ci)*TT+c]=(tg>=0)?res_in[ci*L+tg]:0.0f;}
  }
  for(int k=tid;k<NM*(TT/4);k+=512){int ci=k>>5,c4=k&31;
    ((float4*)(actT+(2*R+ci)*TT))[c4]=((const float4*)(condp+ci*L+t0))[c4];}

  // ---- phase 1: z = Wz @ act (13 tiles of 16 ci, double-buffered weights) ----
  const float* Wz=g_Wz+blk*(KRED*128);
  ((float4*)wbuf)[tid]=((const float4*)Wz)[tid];  // tile 0 -> buf0 (16x128 = 512 float4)
  __syncthreads();

  u64 accF[2][4],accG[2][4];
  #pragma unroll
  for(int j=0;j<2;j++)
    #pragma unroll
    for(int p=0;p<4;p++){accF[j][p]=0ull;accG[j][p]=0ull;}

  for(int kt=0;kt<13;kt++){
    const float* wcur=wbuf+(kt&1)*3072;
    if(kt+1<13){
      float* wnx=wbuf+((kt+1)&1)*3072;
      ((float4*)wnx)[tid]=((const float4*)(Wz+(kt+1)*2048))[tid];
    }
    #pragma unroll
    for(int ci=0;ci<16;ci++){
      const float* wrow=wcur+ci*128;
      float2 wf=*(const float2*)(wrow+a2);
      float2 wg=*(const float2*)(wrow+64+a2);
      const float* arow=actT+(kt*16+ci)*TT;
      ulonglong2 A0=*(const ulonglong2*)(arow+b4);
      ulonglong2 A1=*(const ulonglong2*)(arow+64+b4);
      FMA4(accF[0],wf.x);FMA4(accF[1],wf.y);
      FMA4(accG[0],wg.x);FMA4(accG[1],wg.y);
    }
    __syncthreads();
  }

  // ---- gated activation -> hS ----
  const float* bz=g_bz+blk*128;
  #pragma unroll
  for(int j=0;j<2;j++){
    float bf=bz[a2+j],bg=bz[64+a2+j];
    #pragma unroll
    for(int qp=0;qp<4;qp++){
      float2 f=unpack2(accF[j][qp]);float2 g=unpack2(accG[j][qp]);
      f.x+=bf;f.y+=bf;g.x+=bg;g.y+=bg;
      float2 h;
      h.x=tanhf(f.x)*(1.0f/(1.0f+__expf(-g.x)));
      h.y=tanhf(f.y)*(1.0f/(1.0f+__expf(-g.y)));
      int col=(qp>>1)*64+b4+(qp&1)*2;
      *(float2*)(hS+(a2+j)*TT+col)=h;
    }
  }

  // ---- phase 2: [skip|res] = W2 @ h (4 tiles of 16 ci) ----
  const float* W2=g_W2+blk*(64*192);
  for(int k=tid;k<768;k+=512)((float4*)wbuf)[k]=((const float4*)W2)[k];
  __syncthreads();

  u64 accS[4][4],accR[2][4];
  #pragma unroll
  for(int j=0;j<4;j++)
    #pragma unroll
    for(int p=0;p<4;p++)accS[j][p]=0ull;
  #pragma unroll
  for(int j=0;j<2;j++)
    #pragma unroll
    for(int p=0;p<4;p++)accR[j][p]=0ull;

  for(int kt=0;kt<4;kt++){
    const float* wcur=wbuf+(kt&1)*3072;
    if(kt+1<4){
      float* wnx=wbuf+((kt+1)&1)*3072;
      for(int k=tid;k<768;k+=512)((float4*)wnx)[k]=((const float4*)(W2+(kt+1)*3072))[k];
    }
    #pragma unroll
    for(int ci=0;ci<16;ci++){
      const float* wrow=wcur+ci*192;
      float4 ws=*(const float4*)(wrow+a4);
      float2 wr=*(const float2*)(wrow+128+a2);
      const float* arow=hS+(kt*16+ci)*TT;
      ulonglong2 A0=*(const ulonglong2*)(arow+b4);
      ulonglong2 A1=*(const ulonglong2*)(arow+64+b4);
      FMA4(accS[0],ws.x);FMA4(accS[1],ws.y);FMA4(accS[2],ws.z);FMA4(accS[3],ws.w);
      FMA4(accR[0],wr.x);FMA4(accR[1],wr.y);
    }
    __syncthreads();
  }

  // ---- epilogues ----
  float* skipp=g_skip+bIdx*(S*L);
  #pragma unroll
  for(int j=0;j<4;j++){
    int co=a4+j;float sb=skip_b[blk*S+co];
    #pragma unroll
    for(int q=0;q<2;q++){
      float2 v0=unpack2(accS[j][q*2+0]);float2 v1=unpack2(accS[j][q*2+1]);
      float4 v=make_float4(v0.x+sb,v0.y+sb,v1.x+sb,v1.y+sb);
      float4* dst=(float4*)(skipp+co*L+t0+q*64+b4);
      if(!first){float4 o=*dst;v.x+=o.x;v.y+=o.y;v.z+=o.z;v.w+=o.w;}
      *dst=v;
    }
  }
  #pragma unroll
  for(int j=0;j<2;j++){
    int co=a2+j;float rb=res_b[blk*R+co];
    #pragma unroll
    for(int q=0;q<2;q++){
      float2 v0=unpack2(accR[j][q*2+0]);float2 v1=unpack2(accR[j][q*2+1]);
      float4 cur=*(const float4*)(actT+co*TT+q*64+b4);
      float4 v=make_float4(cur.x+v0.x+rb,cur.y+v0.y+rb,cur.z+v1.x+rb,cur.w+v1.y+rb);
      *(float4*)(res_out+co*L+t0+q*64+b4)=v;
    }
  }
}

// 512 threads post network
__global__ void __launch_bounds__(512,1) post_kernel(const float* __restrict__ p1b,
    const float* __restrict__ p2b,float* __restrict__ out){
  extern __shared__ float sm[];
  float* xS=sm;             // [128][128]
  float* y1S=sm+S*TT;       // [256][128]
  float* wbuf=y1S+NC*TT;    // [2][4096]
  const int tid=threadIdx.x;
  const int a=tid>>4,bb=tid&15;
  const int a4=a*4,b4=bb*4;
  const int bIdx=blockIdx.y;const int t0=blockIdx.x*TT;

  for(int k=tid;k<S*(TT/4);k+=512){int ci=k>>5,c4=k&31;
    float4 v=((const float4*)(g_skip+(bIdx*S+ci)*L+t0))[c4];
    v.x=fmaxf(v.x,0.f);v.y=fmaxf(v.y,0.f);v.z=fmaxf(v.z,0.f);v.w=fmaxf(v.w,0.f);
    ((float4*)(xS+ci*TT))[c4]=v;}

  u64 acc0[4][4],acc1[4][4];
  #pragma unroll
  for(int j=0;j<4;j++)
    #pragma unroll
    for(int p=0;p<4;p++){acc0[j][p]=0ull;acc1[j][p]=0ull;}

  // GEMM1: 8 tiles of 16 ci over S=128
  for(int k=tid;k<1024;k+=512)((float4*)wbuf)[k]=((const float4*)g_Wp1)[k];
  __syncthreads();
  for(int kt=0;kt<8;kt++){
    const float* wcur=wbuf+(kt&1)*4096;
    if(kt+1<8){
      float* wnx=wbuf+((kt+1)&1)*4096;
      for(int k=tid;k<1024;k+=512)((float4*)wnx)[k]=((const float4*)(g_Wp1+(kt+1)*4096))[k];
    }
    #pragma unroll
    for(int ci=0;ci<16;ci++){
      const float* wrow=wcur+ci*256;
      float4 wa=*(const float4*)(wrow+a4);
      float4 wc=*(const float4*)(wrow+128+a4);
      const float* arow=xS+(kt*16+ci)*TT;
      ulonglong2 A0=*(const ulonglong2*)(arow+b4);
      ulonglong2 A1=*(const ulonglong2*)(arow+64+b4);
      FMA4(acc0[0],wa.x);FMA4(acc0[1],wa.y);FMA4(acc0[2],wa.z);FMA4(acc0[3],wa.w);
      FMA4(acc1[0],wc.x);FMA4(acc1[1],wc.y);FMA4(acc1[2],wc.z);FMA4(acc1[3],wc.w);
    }
    __syncthreads();
  }
  #pragma unroll
  for(int j=0;j<4;j++){
    int co0=a4+j,co1=128+a4+j;
    float bb0=p1b[co0],bb1=p1b[co1];
    #pragma unroll
    for(int q=0;q<2;q++){
      float2 u0=unpack2(acc0[j][q*2]);float2 u1=unpack2(acc0[j][q*2+1]);
      *(float4*)(y1S+co0*TT+q*64+b4)=make_float4(fmaxf(u0.x+bb0,0.f),fmaxf(u0.y+bb0,0.f),fmaxf(u1.x+bb0,0.f),fmaxf(u1.y+bb0,0.f));
      float2 s0=unpack2(acc1[j][q*2]);float2 s1=unpack2(acc1[j][q*2+1]);
      *(float4*)(y1S+co1*TT+q*64+b4)=make_float4(fmaxf(s0.x+bb1,0.f),fmaxf(s0.y+bb1,0.f),fmaxf(s1.x+bb1,0.f),fmaxf(s1.y+bb1,0.f));
    }
  }

  // GEMM2: 16 tiles of 16 ci over NC=256
  #pragma unroll
  for(int j=0;j<4;j++)
    #pragma unroll
    for(int p=0;p<4;p++){acc0[j][p]=0ull;acc1[j][p]=0ull;}
  for(int k=tid;k<1024;k+=512)((float4*)wbuf)[k]=((const float4*)g_Wp2)[k];
  __syncthreads();
  for(int kt=0;kt<16;kt++){
    const float* wcur=wbuf+(kt&1)*4096;
    if(kt+1<16){
      float* wnx=wbuf+((kt+1)&1)*4096;
      for(int k=tid;k<1024;k+=512)((float4*)wnx)[k]=((const float4*)(g_Wp2+(kt+1)*4096))[k];
    }
    #pragma unroll
    for(int ci=0;ci<16;ci++){
      const float* wrow=wcur+ci*256;
      float4 wa=*(const float4*)(wrow+a4);
      float4 wc=*(const float4*)(wrow+128+a4);
      const float* arow=y1S+(kt*16+ci)*TT;
      ulonglong2 A0=*(const ulonglong2*)(arow+b4);
      ulonglong2 A1=*(const ulonglong2*)(arow+64+b4);
      FMA4(acc0[0],wa.x);FMA4(acc0[1],wa.y);FMA4(acc0[2],wa.z);FMA4(acc0[3],wa.w);
      FMA4(acc1[0],wc.x);FMA4(acc1[1],wc.y);FMA4(acc1[2],wc.z);FMA4(acc1[3],wc.w);
    }
    __syncthreads();
  }
  #pragma unroll
  for(int j=0;j<4;j++){
    int co0=a4+j,co1=128+a4+j;
    float bb0=p2b[co0],bb1=p2b[co1];
    #pragma unroll
    for(int q=0;q<2;q++){
      float2 u0=unpack2(acc0[j][q*2]);float2 u1=unpack2(acc0[j][q*2+1]);
      *(float4*)(out+(bIdx*NC+co0)*L+t0+q*64+b4)=make_float4(u0.x+bb0,u0.y+bb0,u1.x+bb0,u1.y+bb0);
      float2 s0=unpack2(acc1[j][q*2]);float2 s1=unpack2(acc1[j][q*2+1]);
      *(float4*)(out+(bIdx*NC+co1)*L+t0+q*64+b4)=make_float4(s0.x+bb1,s0.y+bb1,s1.x+bb1,s1.y+bb1);
    }
  }
}

extern "C" void kernel_launch(void* const* d_in, const int* in_sizes, int n_in,
                              void* d_out, int out_size) {
  const float* x      =(const float*)d_in[0];
  const float* mels   =(const float*)d_in[1];
  const float* input_w=(const float*)d_in[2];
  const float* input_b=(const float*)d_in[3];
  const float* mel_w  =(const float*)d_in[4];
  const float* mel_b  =(const float*)d_in[5];
  const float* dil_w  =(const float*)d_in[6];
  const float* dil_b  =(const float*)d_in[7];
  const float* cond_w =(const float*)d_in[8];
  const float* cond_b =(const float*)d_in[9];
  const float* skip_w =(const float*)d_in[10];
  const float* skip_b =(const float*)d_in[11];
  const float* res_w  =(const float*)d_in[12];
  const float* res_b  =(const float*)d_in[13];
  const float* p1w    =(const float*)d_in[14];
  const float* p1b    =(const float*)d_in[15];
  const float* p2w    =(const float*)d_in[16];
  const float* p2b    =(const float*)d_in[17];
  float* out=(float*)d_out;

  const int condSmem=(B*NM*128+160*80)*4;              // 133120
  const int blkSmem=(KRED*TT+64*TT+2*3072)*4;          // 163840
  const int postSmem=(S*TT+NC*TT+2*4096)*4;            // 229376
  cudaFuncSetAttribute(cond_kernel, cudaFuncAttributeMaxDynamicSharedMemorySize, condSmem);
  cudaFuncSetAttribute(block_kernel, cudaFuncAttributeMaxDynamicSharedMemorySize, blkSmem);
  cudaFuncSetAttribute(post_kernel, cudaFuncAttributeMaxDynamicSharedMemorySize, postSmem);

  prep_kernel<<<1024,256>>>(dil_w,dil_b,cond_w,cond_b,skip_w,res_w,p1w,p2w);
  cond_kernel<<<256,256,condSmem>>>(mels,mel_w,mel_b);
  init_res_kernel<<<(B*R*L+255)/256,256>>>(x,input_w,input_b);
  for(int i=0;i<NB;i++){
    int d=1<<(i%MD);
    block_kernel<<<dim3(NTILE,B),512,blkSmem>>>(i,d,i&1,i==0?1:0,skip_b,res_b);
  }
  post_kernel<<<dim3(NTILE,B),512,postSmem>>>(p1b,p2b,out);
}

// round 5
// speedup vs baseline: 1.0389x; 1.0094x over previous
#include <cuda_runtime.h>

typedef unsigned long long u64;
#define DI __device__ __forceinline__

constexpr int B=2, L=32512, R=64, S=128, NM=80, NC=256, NB=30, MD=10;
constexpr int KRED=208, TT=128, NTILE=L/TT; // 254

__device__ __align__(16) float g_cond[B*NM*L];
__device__ __align__(16) float g_res[2][B*R*L];
__device__ __align__(16) float g_skip[B*S*L];
__device__ __align__(16) float g_Wz[NB*KRED*128];
__device__ __align__(16) float g_W2[NB*64*192];
__device__ __align__(16) float g_bz[NB*128];
__device__ __align__(16) float g_Wp1[128*256];
__device__ __align__(16) float g_Wp2[256*256];

DI u64 dup2(float v){u64 r;asm("mov.b64 %0,{%1,%1};":"=l"(r):"f"(v));return r;}
DI void ffma2(u64&d,u64 a,u64 b){asm("fma.rn.f32x2 %0,%1,%2,%0;":"+l"(d):"l"(a),"l"(b));}
DI float2 unpack2(u64 v){float x,y;asm("mov.b64 {%0,%1},%2;":"=f"(x),"=f"(y):"l"(v));return make_float2(x,y);}
// 4 time points (one ulonglong2 A0), one weight scalar
#define FMA2(AC,WS){u64 ww_=dup2(WS);ffma2((AC)[0],ww_,A0.x);ffma2((AC)[1],ww_,A0.y);}
// 8 time points (A0,A1), one weight scalar (post kernel keeps old layout)
#define FMA4(AC,WS){u64 ww_=dup2(WS);ffma2((AC)[0],ww_,A0.x);ffma2((AC)[1],ww_,A0.y);ffma2((AC)[2],ww_,A1.x);ffma2((AC)[3],ww_,A1.y);}

__global__ void prep_kernel(const float* __restrict__ dw,const float* __restrict__ db,
    const float* __restrict__ cw,const float* __restrict__ cb,
    const float* __restrict__ sw,const float* __restrict__ rw,
    const float* __restrict__ p1w,const float* __restrict__ p2w){
  const int N0=NB*KRED*128,N1=NB*64*192,N2=NB*128,N3=128*256,N4=256*256;
  const int total=N0+N1+N2+N3+N4;
  for(int idx=blockIdx.x*blockDim.x+threadIdx.x;idx<total;idx+=gridDim.x*blockDim.x){
    int t=idx;
    if(t<N0){int i=t/(KRED*128);int rem=t%(KRED*128);int j=rem>>7;int co=rem&127;float v;
      if(j<64)v=dw[(((i*128+co)*64)+j)*2+1];
      else if(j<128)v=dw[(((i*128+co)*64)+(j-64))*2+0];
      else v=cw[(i*128+co)*80+(j-128)];
      g_Wz[t]=v;continue;}
    t-=N0;
    if(t<N1){int i=t/(64*192);int rem=t%(64*192);int ci=rem/192;int co=rem%192;
      g_W2[t]=(co<128)?sw[(i*128+co)*64+ci]:rw[(i*64+(co-128))*64+ci];continue;}
    t-=N1;
    if(t<N2){g_bz[t]=db[t]+cb[t];continue;}
    t-=N2;
    if(t<N3){int ci=t>>8;int co=t&255;g_Wp1[t]=p1w[co*128+ci];continue;}
    t-=N3;
    {int ci=t>>8;int co=t&255;g_Wp2[t]=p2w[co*256+ci];}
  }
}

__global__ void cond_kernel(const float* __restrict__ mels,const float* __restrict__ mw,
    const float* __restrict__ mb){
  extern __shared__ float sm[];
  float* melS=sm;               // [B][NM][128]
  float* wS=sm+B*NM*128;        // [160][80]
  const int tid=threadIdx.x;const int r=blockIdx.x;
  for(int k=tid;k<(B*NM*128)/4;k+=256)((float4*)melS)[k]=((const float4*)mels)[k];
  const int k1=255-r,k2=511-r;
  for(int idx=tid;idx<160*80;idx+=256){int j=idx/80,c=idx%80;
    int m=(j<80)?j:(j-80);int k=(j<80)?k1:k2;
    wS[idx]=mw[(c*NM+m)*512+k];}
  __syncthreads();
  for(int idx=tid;idx<B*NM*127;idx+=256){
    int q=idx%127;int c=(idx/127)%NM;int b=idx/(127*NM);
    float acc=mb[c];
    const float* m0=melS+b*NM*128+q;
    #pragma unroll 4
    for(int m=0;m<NM;m++){
      acc+=wS[m*80+c]*m0[m*128]+wS[(80+m)*80+c]*m0[m*128+1];}
    g_cond[(b*NM+c)*L+q*256+r]=acc;
  }
}

__global__ void init_res_kernel(const float* __restrict__ x,const float* __restrict__ iw,
    const float* __restrict__ ib){
  int idx=blockIdx.x*blockDim.x+threadIdx.x;
  if(idx>=B*R*L)return;
  int t=idx%L;int rc=(idx/L)%R;int b=idx/(L*R);
  g_res[0][idx]=iw[rc]*x[b*L+t]+ib[rc];
}

// 512 threads: a=tid>>5 in [0,16) (co group, uniform per warp), bb=tid&31 (time lane)
__global__ void __launch_bounds__(512,1) block_kernel(int blk,int d,int pp,int first,
    const float* __restrict__ skip_b,const float* __restrict__ res_b){
  extern __shared__ float sm[];
  float* actT=sm;            // [208][128]
  float* hS=sm+KRED*TT;      // [64][128]
  float* wbuf=hS+64*TT;      // [2][3072] double buffer
  const int tid=threadIdx.x;
  const int a=tid>>5,bb=tid&31;
  const int a4=a*4,a8=a*8,b4=bb*4;
  const int bIdx=blockIdx.y;const int t0=blockIdx.x*TT;
  const float* res_in=g_res[pp]+bIdx*(R*L);
  float* res_out=g_res[pp^1]+bIdx*(R*L);
  const float* condp=g_cond+bIdx*(NM*L);

  // ---- stage activations [res(t) | res(t-d) | cond] ----
  for(int k=tid;k<R*(TT/4);k+=512){int ci=k>>5,c4=k&31;
    ((float4*)(actT+ci*TT))[c4]=((const float4*)(res_in+ci*L+t0))[c4];}
  if(((d&3)==0)&&(t0>=d)){
    for(int k=tid;k<R*(TT/4);k+=512){int ci=k>>5,c4=k&31;
      ((float4*)(actT+(R+ci)*TT))[c4]=*(const float4*)(res_in+ci*L+t0-d+c4*4);}
  }else{
    for(int k=tid;k<R*TT;k+=512){int ci=k>>7,c=k&(TT-1);
      int tg=t0+c-d;
      actT[(R+ci)*TT+c]=(tg>=0)?res_in[ci*L+tg]:0.0f;}
  }
  for(int k=tid;k<NM*(TT/4);k+=512){int ci=k>>5,c4=k&31;
    ((float4*)(actT+(2*R+ci)*TT))[c4]=((const float4*)(condp+ci*L+t0))[c4];}

  // ---- phase 1: z = Wz @ act; per thread: 4 f-co + 4 g-co, 4 time pts ----
  const float* Wz=g_Wz+blk*(KRED*128);
  ((float4*)wbuf)[tid]=((const float4*)Wz)[tid];  // tile 0: 16x128 = 512 float4
  __syncthreads();

  u64 accF[4][2],accG[4][2];
  #pragma unroll
  for(int j=0;j<4;j++)
    #pragma unroll
    for(int p=0;p<2;p++){accF[j][p]=0ull;accG[j][p]=0ull;}

  for(int kt=0;kt<13;kt++){
    const float* wcur=wbuf+(kt&1)*3072;
    if(kt+1<13){
      float* wnx=wbuf+((kt+1)&1)*3072;
      ((float4*)wnx)[tid]=((const float4*)(Wz+(kt+1)*2048))[tid];
    }
    #pragma unroll
    for(int ci=0;ci<16;ci++){
      const float* wrow=wcur+ci*128;
      float4 wf=*(const float4*)(wrow+a4);      // broadcast (uniform a per warp)
      float4 wg=*(const float4*)(wrow+64+a4);   // broadcast
      const float* arow=actT+(kt*16+ci)*TT;
      ulonglong2 A0=*(const ulonglong2*)(arow+b4);
      FMA2(accF[0],wf.x);FMA2(accF[1],wf.y);FMA2(accF[2],wf.z);FMA2(accF[3],wf.w);
      FMA2(accG[0],wg.x);FMA2(accG[1],wg.y);FMA2(accG[2],wg.z);FMA2(accG[3],wg.w);
    }
    __syncthreads();
  }

  // ---- gated activation -> hS ----
  const float* bz=g_bz+blk*128;
  #pragma unroll
  for(int j=0;j<4;j++){
    float bf=bz[a4+j],bg=bz[64+a4+j];
    float2 f0=unpack2(accF[j][0]),f1=unpack2(accF[j][1]);
    float2 g0=unpack2(accG[j][0]),g1=unpack2(accG[j][1]);
    float4 h;
    h.x=tanhf(f0.x+bf)*(1.0f/(1.0f+__expf(-(g0.x+bg))));
    h.y=tanhf(f0.y+bf)*(1.0f/(1.0f+__expf(-(g0.y+bg))));
    h.z=tanhf(f1.x+bf)*(1.0f/(1.0f+__expf(-(g1.x+bg))));
    h.w=tanhf(f1.y+bf)*(1.0f/(1.0f+__expf(-(g1.y+bg))));
    *(float4*)(hS+(a4+j)*TT+b4)=h;
  }

  // ---- phase 2: [skip|res] = W2 @ h; per thread: 8 skip-co + 4 res-co, 4 t ----
  const float* W2=g_W2+blk*(64*192);
  for(int k=tid;k<768;k+=512)((float4*)wbuf)[k]=((const float4*)W2)[k];
  __syncthreads();

  u64 accS[8][2],accR[4][2];
  #pragma unroll
  for(int j=0;j<8;j++){accS[j][0]=0ull;accS[j][1]=0ull;}
  #pragma unroll
  for(int j=0;j<4;j++){accR[j][0]=0ull;accR[j][1]=0ull;}

  for(int kt=0;kt<4;kt++){
    const float* wcur=wbuf+(kt&1)*3072;
    if(kt+1<4){
      float* wnx=wbuf+((kt+1)&1)*3072;
      for(int k=tid;k<768;k+=512)((float4*)wnx)[k]=((const float4*)(W2+(kt+1)*3072))[k];
    }
    #pragma unroll
    for(int ci=0;ci<16;ci++){
      const float* wrow=wcur+ci*192;
      float4 w0=*(const float4*)(wrow+a8);       // broadcast
      float4 w1=*(const float4*)(wrow+a8+4);     // broadcast
      float4 wr=*(const float4*)(wrow+128+a4);   // broadcast
      const float* arow=hS+(kt*16+ci)*TT;
      ulonglong2 A0=*(const ulonglong2*)(arow+b4);
      FMA2(accS[0],w0.x);FMA2(accS[1],w0.y);FMA2(accS[2],w0.z);FMA2(accS[3],w0.w);
      FMA2(accS[4],w1.x);FMA2(accS[5],w1.y);FMA2(accS[6],w1.z);FMA2(accS[7],w1.w);
      FMA2(accR[0],wr.x);FMA2(accR[1],wr.y);FMA2(accR[2],wr.z);FMA2(accR[3],wr.w);
    }
    __syncthreads();
  }

  // ---- epilogues ----
  float* skipp=g_skip+bIdx*(S*L);
  #pragma unroll
  for(int j=0;j<8;j++){
    int co=a8+j;float sb=skip_b[blk*S+co];
    float2 v0=unpack2(accS[j][0]),v1=unpack2(accS[j][1]);
    float4 v=make_float4(v0.x+sb,v0.y+sb,v1.x+sb,v1.y+sb);
    float4* dst=(float4*)(skipp+co*L+t0+b4);
    if(!first){float4 o=*dst;v.x+=o.x;v.y+=o.y;v.z+=o.z;v.w+=o.w;}
    *dst=v;
  }
  #pragma unroll
  for(int j=0;j<4;j++){
    int co=a4+j;float rb=res_b[blk*R+co];
    float2 v0=unpack2(accR[j][0]),v1=unpack2(accR[j][1]);
    float4 cur=*(const float4*)(actT+co*TT+b4);
    float4 v=make_float4(cur.x+v0.x+rb,cur.y+v0.y+rb,cur.z+v1.x+rb,cur.w+v1.y+rb);
    *(float4*)(res_out+co*L+t0+b4)=v;
  }
}

// 512 threads post network: a=tid>>5 in [0,16) uniform/warp, bb=tid&31
__global__ void __launch_bounds__(512,1) post_kernel(const float* __restrict__ p1b,
    const float* __restrict__ p2b,float* __restrict__ out){
  extern __shared__ float sm[];
  float* xS=sm;             // [128][128]
  float* y1S=sm+S*TT;       // [256][128]
  float* wbuf=y1S+NC*TT;    // [2][4096]
  const int tid=threadIdx.x;
  const int a=tid>>5,bb=tid&31;
  const int a4=a*4,a8=a*8,b4=bb*4;
  const int bIdx=blockIdx.y;const int t0=blockIdx.x*TT;

  for(int k=tid;k<S*(TT/4);k+=512){int ci=k>>5,c4=k&31;
    float4 v=((const float4*)(g_skip+(bIdx*S+ci)*L+t0))[c4];
    v.x=fmaxf(v.x,0.f);v.y=fmaxf(v.y,0.f);v.z=fmaxf(v.z,0.f);v.w=fmaxf(v.w,0.f);
    ((float4*)(xS+ci*TT))[c4]=v;}

  // GEMM1: per thread 16 co (co = a16+j over 256), 4 t
  u64 acc[16][2];
  #pragma unroll
  for(int j=0;j<16;j++){acc[j][0]=0ull;acc[j][1]=0ull;}
  for(int k=tid;k<1024;k+=512)((float4*)wbuf)[k]=((const float4*)g_Wp1)[k];
  __syncthreads();
  for(int kt=0;kt<8;kt++){
    const float* wcur=wbuf+(kt&1)*4096;
    if(kt+1<8){
      float* wnx=wbuf+((kt+1)&1)*4096;
      for(int k=tid;k<1024;k+=512)((float4*)wnx)[k]=((const float4*)(g_Wp1+(kt+1)*4096))[k];
    }
    #pragma unroll
    for(int ci=0;ci<16;ci++){
      const float* wrow=wcur+ci*256;
      float4 wa=*(const float4*)(wrow+a*16);
      float4 wb2=*(const float4*)(wrow+a*16+4);
      float4 wc=*(const float4*)(wrow+a*16+8);
      float4 wd=*(const float4*)(wrow+a*16+12);
      const float* arow=xS+(kt*16+ci)*TT;
      ulonglong2 A0=*(const ulonglong2*)(arow+b4);
      FMA2(acc[0],wa.x);FMA2(acc[1],wa.y);FMA2(acc[2],wa.z);FMA2(acc[3],wa.w);
      FMA2(acc[4],wb2.x);FMA2(acc[5],wb2.y);FMA2(acc[6],wb2.z);FMA2(acc[7],wb2.w);
      FMA2(acc[8],wc.x);FMA2(acc[9],wc.y);FMA2(acc[10],wc.z);FMA2(acc[11],wc.w);
      FMA2(acc[12],wd.x);FMA2(acc[13],wd.y);FMA2(acc[14],wd.z);FMA2(acc[15],wd.w);
    }
    __syncthreads();
  }
  #pragma unroll
  for(int j=0;j<16;j++){
    int co=a*16+j;float bb0=p1b[co];
    float2 u0=unpack2(acc[j][0]),u1=unpack2(acc[j][1]);
    *(float4*)(y1S+co*TT+b4)=make_float4(fmaxf(u0.x+bb0,0.f),fmaxf(u0.y+bb0,0.f),
                                         fmaxf(u1.x+bb0,0.f),fmaxf(u1.y+bb0,0.f));
  }

  // GEMM2
  #pragma unroll
  for(int j=0;j<16;j++){acc[j][0]=0ull;acc[j][1]=0ull;}
  for(int k=tid;k<1024;k+=512)((float4*)wbuf)[k]=((const float4*)g_Wp2)[k];
  __syncthreads();
  for(int kt=0;kt<16;kt++){
    const float* wcur=wbuf+(kt&1)*4096;
    if(kt+1<16){
      float* wnx=wbuf+((kt+1)&1)*4096;
      for(int k=tid;k<1024;k+=512)((float4*)wnx)[k]=((const float4*)(g_Wp2+(kt+1)*4096))[k];
    }
    #pragma unroll
    for(int ci=0;ci<16;ci++){
      const float* wrow=wcur+ci*256;
      float4 wa=*(const float4*)(wrow+a*16);
      float4 wb2=*(const float4*)(wrow+a*16+4);
      float4 wc=*(const float4*)(wrow+a*16+8);
      float4 wd=*(const float4*)(wrow+a*16+12);
      const float* arow=y1S+(kt*16+ci)*TT;
      ulonglong2 A0=*(const ulonglong2*)(arow+b4);
      FMA2(acc[0],wa.x);FMA2(acc[1],wa.y);FMA2(acc[2],wa.z);FMA2(acc[3],wa.w);
      FMA2(acc[4],wb2.x);FMA2(acc[5],wb2.y);FMA2(acc[6],wb2.z);FMA2(acc[7],wb2.w);
      FMA2(acc[8],wc.x);FMA2(acc[9],wc.y);FMA2(acc[10],wc.z);FMA2(acc[11],wc.w);
      FMA2(acc[12],wd.x);FMA2(acc[13],wd.y);FMA2(acc[14],wd.z);FMA2(acc[15],wd.w);
    }
    __syncthreads();
  }
  #pragma unroll
  for(int j=0;j<16;j++){
    int co=a*16+j;float bb0=p2b[co];
    float2 u0=unpack2(acc[j][0]),u1=unpack2(acc[j][1]);
    *(float4*)(out+(bIdx*NC+co)*L+t0+b4)=make_float4(u0.x+bb0,u0.y+bb0,u1.x+bb0,u1.y+bb0);
  }
}

extern "C" void kernel_launch(void* const* d_in, const int* in_sizes, int n_in,
                              void* d_out, int out_size) {
  const float* x      =(const float*)d_in[0];
  const float* mels   =(const float*)d_in[1];
  const float* input_w=(const float*)d_in[2];
  const float* input_b=(const float*)d_in[3];
  const float* mel_w  =(const float*)d_in[4];
  const float* mel_b  =(const float*)d_in[5];
  const float* dil_w  =(const float*)d_in[6];
  const float* dil_b  =(const float*)d_in[7];
  const float* cond_w =(const float*)d_in[8];
  const float* cond_b =(const float*)d_in[9];
  const float* skip_w =(const float*)d_in[10];
  const float* skip_b =(const float*)d_in[11];
  const float* res_w  =(const float*)d_in[12];
  const float* res_b  =(const float*)d_in[13];
  const float* p1w    =(const float*)d_in[14];
  const float* p1b    =(const float*)d_in[15];
  const float* p2w    =(const float*)d_in[16];
  const float* p2b    =(const float*)d_in[17];
  float* out=(float*)d_out;

  const int condSmem=(B*NM*128+160*80)*4;              // 133120
  const int blkSmem=(KRED*TT+64*TT+2*3072)*4;          // 163840
  const int postSmem=(S*TT+NC*TT+2*4096)*4;            // 229376
  cudaFuncSetAttribute(cond_kernel, cudaFuncAttributeMaxDynamicSharedMemorySize, condSmem);
  cudaFuncSetAttribute(block_kernel, cudaFuncAttributeMaxDynamicSharedMemorySize, blkSmem);
  cudaFuncSetAttribute(post_kernel, cudaFuncAttributeMaxDynamicSharedMemorySize, postSmem);

  prep_kernel<<<1024,256>>>(dil_w,dil_b,cond_w,cond_b,skip_w,res_w,p1w,p2w);
  cond_kernel<<<256,256,condSmem>>>(mels,mel_w,mel_b);
  init_res_kernel<<<(B*R*L+255)/256,256>>>(x,input_w,input_b);
  for(int i=0;i<NB;i++){
    int d=1<<(i%MD);
    block_kernel<<<dim3(NTILE,B),512,blkSmem>>>(i,d,i&1,i==0?1:0,skip_b,res_b);
  }
  post_kernel<<<dim3(NTILE,B),512,postSmem>>>(p1b,p2b,out);
}

// round 7
// speedup vs baseline: 1.6893x; 1.6260x over previous
#include <cuda_runtime.h>
#include <cuda_bf16.h>

typedef unsigned long long u64;
typedef unsigned int u32;
typedef unsigned short u16;
#define DI __device__ __forceinline__

constexpr int B=2, L=32512, R=64, S=128, NM=80, NC=256, NB=30, MD=10;
constexpr int KRED=208, TT=128, NTILE=L/TT; // 254
constexpr int TN=128, NT2=L/TN;             // 254

// persistent state
__device__ __align__(16) float g_cond[B*NM*L];
__device__ __align__(16) float g_res[2][B*R*L];
__device__ __align__(16) float g_skip[B*S*L];
__device__ __align__(16) float g_bz[NB*128];
__device__ __align__(16) float g_Wp1[128*256];
__device__ __align__(16) float g_Wp2[256*256];
// bf16 split weights in final smem layouts
// A1: [blk][2(h,l)][128 co][216 k]   (k 0..207 valid)
__device__ __align__(16) u16 g_A1[NB*2*128*216];
// A2: [blk][2(h,l)][192 co][72 k]    (co 0..127 skip, 128..191 res; k 0..63)
__device__ __align__(16) u16 g_A2[NB*2*192*72];

// pitches (bf16 units / bytes)
constexpr int PA1=216, PA1B=432;
constexpr int PB =136, PBB =272;
constexpr int PA2=72,  PA2B=144;
constexpr int PZ =132;                       // zbuf float pitch

// smem layout (bytes)
constexpr int A1HALF = 128*PA1*2;            // 55296
constexpr int OFF_A1H = 0;
constexpr int OFF_A1L = A1HALF;              // 55296
constexpr int B1HALF = KRED*PBB;             // 56576
constexpr int OFF_B1H = 2*A1HALF;            // 110592
constexpr int OFF_B1L = OFF_B1H + B1HALF;    // 167168
constexpr int SMEM_MMA = OFF_B1L + B1HALF;   // 223744
// phase-2 aliases
constexpr int OFF_ZBUF = 0;                  // 192*132*4 = 101376
constexpr int A2HALF = 192*PA2B;             // 27648
constexpr int OFF_A2H = 101376;
constexpr int OFF_A2L = OFF_A2H + A2HALF;    // 129024
constexpr int B2HALF = 64*PBB;               // 17408
constexpr int OFF_B2H = OFF_A2L + A2HALF;    // 156672
constexpr int OFF_B2L = OFF_B2H + B2HALF;    // 174080  (+17408 = 191488 <= 223744)

// ---------- helpers ----------
DI u16 f2bf(float x){ u16 u; asm("cvt.rn.bf16.f32 %0, %1;" : "=h"(u) : "f"(x)); return u; }
DI float bf2f(u16 u){ return __uint_as_float(((u32)u)<<16); }
DI u32 smem_u32(const void* p){ u32 a; asm("{ .reg .u64 t; cvta.to.shared.u64 t, %1; cvt.u32.u64 %0, t; }" : "=r"(a) : "l"(p)); return a; }
DI void ldm4(u32* r, u32 addr){
  asm volatile("ldmatrix.sync.aligned.m8n8.x4.shared.b16 {%0,%1,%2,%3},[%4];"
    : "=r"(r[0]),"=r"(r[1]),"=r"(r[2]),"=r"(r[3]) : "r"(addr));
}
DI void ldm4t(u32* r, u32 addr){
  asm volatile("ldmatrix.sync.aligned.m8n8.x4.trans.shared.b16 {%0,%1,%2,%3},[%4];"
    : "=r"(r[0]),"=r"(r[1]),"=r"(r[2]),"=r"(r[3]) : "r"(addr));
}
DI void mma16816(float* d, const u32* a, const u32* b){
  asm volatile("mma.sync.aligned.m16n8k16.row.col.f32.bf16.bf16.f32 "
    "{%0,%1,%2,%3},{%4,%5,%6,%7},{%8,%9},{%0,%1,%2,%3};"
    : "+f"(d[0]),"+f"(d[1]),"+f"(d[2]),"+f"(d[3])
    : "r"(a[0]),"r"(a[1]),"r"(a[2]),"r"(a[3]),"r"(b[0]),"r"(b[1]));
}

// ---------------- prep: pack weights as bf16 hi/lo ----------------
__global__ void prep_kernel(const float* __restrict__ dw,const float* __restrict__ db,
    const float* __restrict__ cw,const float* __restrict__ cb,
    const float* __restrict__ sw,const float* __restrict__ rw,
    const float* __restrict__ p1w,const float* __restrict__ p2w){
  const int NA1=NB*128*PA1, NA2=NB*192*PA2;
  const int N2=NB*128, N3=128*256, N4=256*256;
  const int total=NA1+NA2+N2+N3+N4;
  for(int idx=blockIdx.x*blockDim.x+threadIdx.x;idx<total;idx+=gridDim.x*blockDim.x){
    int t=idx;
    if(t<NA1){
      int blk=t/(128*PA1); int rem=t%(128*PA1); int co=rem/PA1; int k=rem%PA1;
      float v=0.f;
      if(k<64)        v=dw[((blk*128+co)*64+k)*2+1];
      else if(k<128)  v=dw[((blk*128+co)*64+(k-64))*2+0];
      else if(k<KRED) v=cw[(blk*128+co)*80+(k-128)];
      u16 hi=f2bf(v), lo=f2bf(v-bf2f(hi));
      int base=blk*2*128*PA1;
      g_A1[base+co*PA1+k]=hi; g_A1[base+128*PA1+co*PA1+k]=lo;
      continue;
    }
    t-=NA1;
    if(t<NA2){
      int blk=t/(192*PA2); int rem=t%(192*PA2); int co=rem/PA2; int k=rem%PA2;
      float v=0.f;
      if(k<64) v=(co<128)?sw[(blk*128+co)*64+k]:rw[(blk*64+(co-128))*64+k];
      u16 hi=f2bf(v), lo=f2bf(v-bf2f(hi));
      int base=blk*2*192*PA2;
      g_A2[base+co*PA2+k]=hi; g_A2[base+192*PA2+co*PA2+k]=lo;
      continue;
    }
    t-=NA2;
    if(t<N2){ g_bz[t]=db[t]+cb[t]; continue; }
    t-=N2;
    if(t<N3){ int ci=t>>8; int co=t&255; g_Wp1[t]=p1w[co*128+ci]; continue; }
    t-=N3;
    { int ci=t>>8; int co=t&255; g_Wp2[t]=p2w[co*256+ci]; }
  }
}

// ---------------- cond upsample ----------------
__global__ void cond_kernel(const float* __restrict__ mels,const float* __restrict__ mw,
    const float* __restrict__ mb){
  extern __shared__ float sm[];
  float* melS=sm;               // [B][NM][128]
  float* wS=sm+B*NM*128;        // [160][80]
  const int tid=threadIdx.x;const int r=blockIdx.x;
  for(int k=tid;k<(B*NM*128)/4;k+=256)((float4*)melS)[k]=((const float4*)mels)[k];
  const int k1=255-r,k2=511-r;
  for(int idx=tid;idx<160*80;idx+=256){int j=idx/80,c=idx%80;
    int m=(j<80)?j:(j-80);int k=(j<80)?k1:k2;
    wS[idx]=mw[(c*NM+m)*512+k];}
  __syncthreads();
  for(int idx=tid;idx<B*NM*127;idx+=256){
    int q=idx%127;int c=(idx/127)%NM;int b=idx/(127*NM);
    float acc=mb[c];
    const float* m0=melS+b*NM*128+q;
    #pragma unroll 4
    for(int m=0;m<NM;m++){
      acc+=wS[m*80+c]*m0[m*128]+wS[(80+m)*80+c]*m0[m*128+1];}
    g_cond[(b*NM+c)*L+q*256+r]=acc;
  }
}

__global__ void init_res_kernel(const float* __restrict__ x,const float* __restrict__ iw,
    const float* __restrict__ ib){
  int idx=blockIdx.x*blockDim.x+threadIdx.x;
  if(idx>=B*R*L)return;
  int t=idx%L;int rc=(idx/L)%R;int b=idx/(L*R);
  g_res[0][idx]=iw[rc]*x[b*L+t]+ib[rc];
}

// ---------------- mma.sync WaveNet block ----------------
__global__ void __launch_bounds__(512,1) mma_block_kernel(int blk,int d,int pp,int first,
    const float* __restrict__ skip_b,const float* __restrict__ res_b){
  extern __shared__ char smc[];
  const u32 sb=smem_u32(smc);
  const int tid=threadIdx.x;
  const int wid=tid>>5, lane=tid&31;
  const int bIdx=blockIdx.y;
  const int t0=blockIdx.x*TN;
  const float* res_in=g_res[pp]+bIdx*(R*L);
  float*       res_out=g_res[pp^1]+bIdx*(R*L);
  const float* condp=g_cond+bIdx*(NM*L);
  float*       skipp=g_skip+bIdx*(S*L);
  float* zbuf=(float*)(smc+OFF_ZBUF);

  // ---- stage B1: act [k=208][t=128] bf16 hi/lo, pitch 136 ----
  const bool ad=((d&3)==0)&&(t0>=d);
  for(int k=tid;k<KRED*32;k+=512){
    int row=k>>5, c4=k&31;
    float4 v;
    if(row<64){ v=*(const float4*)(res_in+row*L+t0+c4*4); }
    else if(row<128){
      int ci=row-64;
      if(ad){ v=*(const float4*)(res_in+ci*L+t0-d+c4*4); }
      else{
        int tb=t0+c4*4-d;
        v.x=(tb  >=0)?res_in[ci*L+tb  ]:0.f;
        v.y=(tb+1>=0)?res_in[ci*L+tb+1]:0.f;
        v.z=(tb+2>=0)?res_in[ci*L+tb+2]:0.f;
        v.w=(tb+3>=0)?res_in[ci*L+tb+3]:0.f;
      }
    }else{ v=*(const float4*)(condp+(row-128)*L+t0+c4*4); }
    u16 h0=f2bf(v.x),h1=f2bf(v.y),h2=f2bf(v.z),h3=f2bf(v.w);
    u16 l0=f2bf(v.x-bf2f(h0)),l1=f2bf(v.y-bf2f(h1)),l2=f2bf(v.z-bf2f(h2)),l3=f2bf(v.w-bf2f(h3));
    u32 off=(u32)(row*PBB+c4*8);
    *(uint2*)(smc+OFF_B1H+off)=make_uint2((u32)h0|((u32)h1<<16),(u32)h2|((u32)h3<<16));
    *(uint2*)(smc+OFF_B1L+off)=make_uint2((u32)l0|((u32)l1<<16),(u32)l2|((u32)l3<<16));
  }
  // ---- copy A1 (both halves contiguous): 110592 B = 6912 uint4 ----
  {
    const uint4* src=(const uint4*)(g_A1+(size_t)blk*2*128*PA1);
    uint4* dst=(uint4*)(smc+OFF_A1H);
    #pragma unroll
    for(int i=0;i<14;i++){ int k=tid+i*512; if(k<6912) dst[k]=src[k]; }
  }
  __syncthreads();

  // ---- GEMM1: 16 warps, warp tile 32co x 32t, K=208 ----
  {
    const int cg=wid>>2, tg=wid&3;
    const int co0=cg*32, tw0=tg*32;
    float acc[2][4][4];
    #pragma unroll
    for(int m=0;m<2;m++)
      #pragma unroll
      for(int n=0;n<4;n++)
        #pragma unroll
        for(int q=0;q<4;q++) acc[m][n][q]=0.f;

    u32 aAH[2], aAL[2], bAH[2], bAL[2];
    #pragma unroll
    for(int m=0;m<2;m++){
      u32 ro=(u32)((co0+m*16+(lane&15))*PA1B+(lane>>4)*16);
      aAH[m]=sb+OFF_A1H+ro; aAL[m]=sb+OFF_A1L+ro;
    }
    #pragma unroll
    for(int s=0;s<2;s++){
      u32 ro=(u32)((lane&15)*PBB+(tw0+s*16+(lane>>4)*8)*2);
      bAH[s]=sb+OFF_B1H+ro; bAL[s]=sb+OFF_B1L+ro;
    }
    for(int ks=0;ks<13;ks++){
      u32 ah[2][4],al[2][4],bh[2][4],bl[2][4];
      #pragma unroll
      for(int m=0;m<2;m++){ ldm4(ah[m],aAH[m]+ks*32); ldm4(al[m],aAL[m]+ks*32); }
      #pragma unroll
      for(int s=0;s<2;s++){ ldm4t(bh[s],bAH[s]+ks*16*PBB); ldm4t(bl[s],bAL[s]+ks*16*PBB); }
      #pragma unroll
      for(int m=0;m<2;m++)
        #pragma unroll
        for(int n=0;n<4;n++){
          const u32* ph=&bh[n>>1][(n&1)*2];
          const u32* pl=&bl[n>>1][(n&1)*2];
          mma16816(acc[m][n], ah[m], ph);
          mma16816(acc[m][n], ah[m], pl);
          mma16816(acc[m][n], al[m], ph);
        }
    }
    __syncthreads();   // A1/B1 consumed; smem can be reused
    // write z to zbuf
    #pragma unroll
    for(int m=0;m<2;m++)
      #pragma unroll
      for(int n=0;n<4;n++){
        int co=co0+m*16+(lane>>2);
        int tt=tw0+n*8+(lane&3)*2;
        *(float2*)(zbuf+co*PZ+tt)      =make_float2(acc[m][n][0],acc[m][n][1]);
        *(float2*)(zbuf+(co+8)*PZ+tt)  =make_float2(acc[m][n][2],acc[m][n][3]);
      }
  }
  // ---- copy A2: 55296 B = 3456 uint4 ----
  {
    const uint4* src=(const uint4*)(g_A2+(size_t)blk*2*192*PA2);
    uint4* dst=(uint4*)(smc+OFF_A2H);
    #pragma unroll
    for(int i=0;i<7;i++){ int k=tid+i*512; if(k<3456) dst[k]=src[k]; }
  }
  __syncthreads();

  // ---- gate: h = tanh(f)*sigmoid(g) -> B2 hi/lo [64k][128t] ----
  {
    int ci=tid>>3, t16=(tid&7)*16;
    float bzf=g_bz[blk*128+ci], bzg=g_bz[blk*128+64+ci];
    u16 hh[16], hl[16];
    #pragma unroll
    for(int i=0;i<16;i++){
      float f=zbuf[ci*PZ+t16+i]+bzf;
      float g=zbuf[(64+ci)*PZ+t16+i]+bzg;
      float h=tanhf(f)*(1.0f/(1.0f+__expf(-g)));
      hh[i]=f2bf(h); hl[i]=f2bf(h-bf2f(hh[i]));
    }
    u32 off=(u32)(ci*PBB+t16*2);
    #pragma unroll
    for(int q=0;q<2;q++){
      *(uint4*)(smc+OFF_B2H+off+q*16)=make_uint4(
        (u32)hh[q*8+0]|((u32)hh[q*8+1]<<16),(u32)hh[q*8+2]|((u32)hh[q*8+3]<<16),
        (u32)hh[q*8+4]|((u32)hh[q*8+5]<<16),(u32)hh[q*8+6]|((u32)hh[q*8+7]<<16));
      *(uint4*)(smc+OFF_B2L+off+q*16)=make_uint4(
        (u32)hl[q*8+0]|((u32)hl[q*8+1]<<16),(u32)hl[q*8+2]|((u32)hl[q*8+3]<<16),
        (u32)hl[q*8+4]|((u32)hl[q*8+5]<<16),(u32)hl[q*8+6]|((u32)hl[q*8+7]<<16));
    }
  }
  __syncthreads();

  // ---- GEMM2: D[192co][128t], 24 tiles of 32co x 32t over 16 warps ----
  for(int tp=0;tp<2;tp++){
    int tau=wid+tp*16;
    if(tau<24){
      int cg=tau>>2, tg=tau&3;
      int co0=cg*32, tw0=tg*32;
      float acc[2][4][4];
      #pragma unroll
      for(int m=0;m<2;m++)
        #pragma unroll
        for(int n=0;n<4;n++)
          #pragma unroll
          for(int q=0;q<4;q++) acc[m][n][q]=0.f;
      u32 aAH[2],aAL[2],bAH[2],bAL[2];
      #pragma unroll
      for(int m=0;m<2;m++){
        u32 ro=(u32)((co0+m*16+(lane&15))*PA2B+(lane>>4)*16);
        aAH[m]=sb+OFF_A2H+ro; aAL[m]=sb+OFF_A2L+ro;
      }
      #pragma unroll
      for(int s=0;s<2;s++){
        u32 ro=(u32)((lane&15)*PBB+(tw0+s*16+(lane>>4)*8)*2);
        bAH[s]=sb+OFF_B2H+ro; bAL[s]=sb+OFF_B2L+ro;
      }
      #pragma unroll
      for(int ks=0;ks<4;ks++){
        u32 ah[2][4],al[2][4],bh[2][4],bl[2][4];
        #pragma unroll
        for(int m=0;m<2;m++){ ldm4(ah[m],aAH[m]+ks*32); ldm4(al[m],aAL[m]+ks*32); }
        #pragma unroll
        for(int s=0;s<2;s++){ ldm4t(bh[s],bAH[s]+ks*16*PBB); ldm4t(bl[s],bAL[s]+ks*16*PBB); }
        #pragma unroll
        for(int m=0;m<2;m++)
          #pragma unroll
          for(int n=0;n<4;n++){
            const u32* ph=&bh[n>>1][(n&1)*2];
            const u32* pl=&bl[n>>1][(n&1)*2];
            mma16816(acc[m][n], ah[m], ph);
            mma16816(acc[m][n], ah[m], pl);
            mma16816(acc[m][n], al[m], ph);
          }
      }
      #pragma unroll
      for(int m=0;m<2;m++)
        #pragma unroll
        for(int n=0;n<4;n++){
          int co=co0+m*16+(lane>>2);
          int tt=tw0+n*8+(lane&3)*2;
          *(float2*)(zbuf+co*PZ+tt)    =make_float2(acc[m][n][0],acc[m][n][1]);
          *(float2*)(zbuf+(co+8)*PZ+tt)=make_float2(acc[m][n][2],acc[m][n][3]);
        }
    }
  }
  __syncthreads();

  // ---- epilogues: skip RMW + res write ----
  #pragma unroll
  for(int i=0;i<8;i++){
    int k=tid+i*512;               // 4096 chunks: 128co x 32 float4
    int co=k>>5, c4=k&31; int tt=c4*4;
    float sb0=skip_b[blk*S+co];
    float4 v=make_float4(zbuf[co*PZ+tt]+sb0, zbuf[co*PZ+tt+1]+sb0,
                         zbuf[co*PZ+tt+2]+sb0, zbuf[co*PZ+tt+3]+sb0);
    float4* dst=(float4*)(skipp+co*L+t0+tt);
    if(!first){ float4 o=*dst; v.x+=o.x;v.y+=o.y;v.z+=o.z;v.w+=o.w; }
    *dst=v;
  }
  #pragma unroll
  for(int i=0;i<4;i++){
    int k=tid+i*512;               // 2048 chunks: 64co x 32 float4
    int co=k>>5, c4=k&31; int tt=c4*4;
    float rb=res_b[blk*R+co];
    const float* zr=zbuf+(128+co)*PZ+tt;
    float4 cur=*(const float4*)(res_in+co*L+t0+tt);
    float4 v=make_float4(cur.x+zr[0]+rb,cur.y+zr[1]+rb,cur.z+zr[2]+rb,cur.w+zr[3]+rb);
    *(float4*)(res_out+co*L+t0+tt)=v;
  }
}

// ---------------- SIMT post network ----------------
DI u64 dup2(float v){u64 r;asm("mov.b64 %0,{%1,%1};":"=l"(r):"f"(v));return r;}
DI void ffma2(u64&d,u64 a,u64 b){asm("fma.rn.f32x2 %0,%1,%2,%0;":"+l"(d):"l"(a),"l"(b));}
DI float2 unpack2(u64 v){float x,y;asm("mov.b64 {%0,%1},%2;":"=f"(x),"=f"(y):"l"(v));return make_float2(x,y);}
#define FMA2(AC,WS){u64 ww_=dup2(WS);ffma2((AC)[0],ww_,A0.x);ffma2((AC)[1],ww_,A0.y);}

__global__ void __launch_bounds__(512,1) post_kernel(const float* __restrict__ p1b,
    const float* __restrict__ p2b,float* __restrict__ out){
  extern __shared__ float sm[];
  float* xS=sm;             // [128][128]
  float* y1S=sm+S*TT;       // [256][128]
  float* wbuf=y1S+NC*TT;    // [2][4096]
  const int tid=threadIdx.x;
  const int a=tid>>5,bb=tid&31;
  const int b4=bb*4;
  const int bIdx=blockIdx.y;const int t0=blockIdx.x*TT;

  for(int k=tid;k<S*(TT/4);k+=512){int ci=k>>5,c4=k&31;
    float4 v=((const float4*)(g_skip+(bIdx*S+ci)*L+t0))[c4];
    v.x=fmaxf(v.x,0.f);v.y=fmaxf(v.y,0.f);v.z=fmaxf(v.z,0.f);v.w=fmaxf(v.w,0.f);
    ((float4*)(xS+ci*TT))[c4]=v;}

  u64 acc[16][2];
  #pragma unroll
  for(int j=0;j<16;j++){acc[j][0]=0ull;acc[j][1]=0ull;}
  for(int k=tid;k<1024;k+=512)((float4*)wbuf)[k]=((const float4*)g_Wp1)[k];
  __syncthreads();
  for(int kt=0;kt<8;kt++){
    const float* wcur=wbuf+(kt&1)*4096;
    if(kt+1<8){
      float* wnx=wbuf+((kt+1)&1)*4096;
      for(int k=tid;k<1024;k+=512)((float4*)wnx)[k]=((const float4*)(g_Wp1+(kt+1)*4096))[k];
    }
    #pragma unroll
    for(int ci=0;ci<16;ci++){
      const float* wrow=wcur+ci*256;
      float4 wa=*(const float4*)(wrow+a*16);
      float4 wb2=*(const float4*)(wrow+a*16+4);
      float4 wc=*(const float4*)(wrow+a*16+8);
      float4 wd=*(const float4*)(wrow+a*16+12);
      const float* arow=xS+(kt*16+ci)*TT;
      ulonglong2 A0=*(const ulonglong2*)(arow+b4);
      FMA2(acc[0],wa.x);FMA2(acc[1],wa.y);FMA2(acc[2],wa.z);FMA2(acc[3],wa.w);
      FMA2(acc[4],wb2.x);FMA2(acc[5],wb2.y);FMA2(acc[6],wb2.z);FMA2(acc[7],wb2.w);
      FMA2(acc[8],wc.x);FMA2(acc[9],wc.y);FMA2(acc[10],wc.z);FMA2(acc[11],wc.w);
      FMA2(acc[12],wd.x);FMA2(acc[13],wd.y);FMA2(acc[14],wd.z);FMA2(acc[15],wd.w);
    }
    __syncthreads();
  }
  #pragma unroll
  for(int j=0;j<16;j++){
    int co=a*16+j;float bb0=p1b[co];
    float2 u0=unpack2(acc[j][0]),u1=unpack2(acc[j][1]);
    *(float4*)(y1S+co*TT+b4)=make_float4(fmaxf(u0.x+bb0,0.f),fmaxf(u0.y+bb0,0.f),
                                         fmaxf(u1.x+bb0,0.f),fmaxf(u1.y+bb0,0.f));
  }

  #pragma unroll
  for(int j=0;j<16;j++){acc[j][0]=0ull;acc[j][1]=0ull;}
  for(int k=tid;k<1024;k+=512)((float4*)wbuf)[k]=((const float4*)g_Wp2)[k];
  __syncthreads();
  for(int kt=0;kt<16;kt++){
    const float* wcur=wbuf+(kt&1)*4096;
    if(kt+1<16){
      float* wnx=wbuf+((kt+1)&1)*4096;
      for(int k=tid;k<1024;k+=512)((float4*)wnx)[k]=((const float4*)(g_Wp2+(kt+1)*4096))[k];
    }
    #pragma unroll
    for(int ci=0;ci<16;ci++){
      const float* wrow=wcur+ci*256;
      float4 wa=*(const float4*)(wrow+a*16);
      float4 wb2=*(const float4*)(wrow+a*16+4);
      float4 wc=*(const float4*)(wrow+a*16+8);
      float4 wd=*(const float4*)(wrow+a*16+12);
      const float* arow=y1S+(kt*16+ci)*TT;
      ulonglong2 A0=*(const ulonglong2*)(arow+b4);
      FMA2(acc[0],wa.x);FMA2(acc[1],wa.y);FMA2(acc[2],wa.z);FMA2(acc[3],wa.w);
      FMA2(acc[4],wb2.x);FMA2(acc[5],wb2.y);FMA2(acc[6],wb2.z);FMA2(acc[7],wb2.w);
      FMA2(acc[8],wc.x);FMA2(acc[9],wc.y);FMA2(acc[10],wc.z);FMA2(acc[11],wc.w);
      FMA2(acc[12],wd.x);FMA2(acc[13],wd.y);FMA2(acc[14],wd.z);FMA2(acc[15],wd.w);
    }
    __syncthreads();
  }
  #pragma unroll
  for(int j=0;j<16;j++){
    int co=a*16+j;float bb0=p2b[co];
    float2 u0=unpack2(acc[j][0]),u1=unpack2(acc[j][1]);
    *(float4*)(out+(bIdx*NC+co)*L+t0+b4)=make_float4(u0.x+bb0,u0.y+bb0,u1.x+bb0,u1.y+bb0);
  }
}

extern "C" void kernel_launch(void* const* d_in, const int* in_sizes, int n_in,
                              void* d_out, int out_size) {
  const float* x      =(const float*)d_in[0];
  const float* mels   =(const float*)d_in[1];
  const float* input_w=(const float*)d_in[2];
  const float* input_b=(const float*)d_in[3];
  const float* mel_w  =(const float*)d_in[4];
  const float* mel_b  =(const float*)d_in[5];
  const float* dil_w  =(const float*)d_in[6];
  const float* dil_b  =(const float*)d_in[7];
  const float* cond_w =(const float*)d_in[8];
  const float* cond_b =(const float*)d_in[9];
  const float* skip_w =(const float*)d_in[10];
  const float* skip_b =(const float*)d_in[11];
  const float* res_w  =(const float*)d_in[12];
  const float* res_b  =(const float*)d_in[13];
  const float* p1w    =(const float*)d_in[14];
  const float* p1b    =(const float*)d_in[15];
  const float* p2w    =(const float*)d_in[16];
  const float* p2b    =(const float*)d_in[17];
  float* out=(float*)d_out;

  const int condSmem=(B*NM*128+160*80)*4;
  const int postSmem=(S*TT+NC*TT+2*4096)*4;
  cudaFuncSetAttribute(cond_kernel, cudaFuncAttributeMaxDynamicSharedMemorySize, condSmem);
  cudaFuncSetAttribute(mma_block_kernel, cudaFuncAttributeMaxDynamicSharedMemorySize, SMEM_MMA);
  cudaFuncSetAttribute(post_kernel, cudaFuncAttributeMaxDynamicSharedMemorySize, postSmem);

  prep_kernel<<<1024,256>>>(dil_w,dil_b,cond_w,cond_b,skip_w,res_w,p1w,p2w);
  cond_kernel<<<256,256,condSmem>>>(mels,mel_w,mel_b);
  init_res_kernel<<<(B*R*L+255)/256,256>>>(x,input_w,input_b);
  for(int i=0;i<NB;i++){
    int d=1<<(i%MD);
    mma_block_kernel<<<dim3(NT2,B),512,SMEM_MMA>>>(i,d,i&1,i==0?1:0,skip_b,res_b);
  }
  post_kernel<<<dim3(NTILE,B),512,postSmem>>>(p1b,p2b,out);
}

// round 9
// speedup vs baseline: 1.6966x; 1.0043x over previous
#include <cuda_runtime.h>
#include <cuda_bf16.h>

typedef unsigned long long u64;
typedef unsigned int u32;
typedef unsigned short u16;
#define DI __device__ __forceinline__

constexpr int B=2, L=32512, R=64, S=128, NM=80, NC=256, NB=30, MD=10;
constexpr int KRED=208, TT=128, NTILE=L/TT; // 254
constexpr int TN=128, NT2=L/TN;             // 254

// persistent state
__device__ __align__(16) float g_cond[B*NM*L];
__device__ __align__(16) float g_res[2][B*R*L];
__device__ __align__(16) float g_skip[B*S*L];
__device__ __align__(16) float g_bz[NB*128];
// bf16 split weights in final smem layouts
__device__ __align__(16) u16 g_A1[NB*2*128*216];  // [blk][h|l][128 co][216 k]
__device__ __align__(16) u16 g_A2[NB*2*192*72];   // [blk][h|l][192 co][72 k]
// post weights, bf16 hi/lo planes, row-major [co][k]
__device__ __align__(16) u16 g_P1h[256*128];
__device__ __align__(16) u16 g_P1l[256*128];
__device__ __align__(16) u16 g_P2h[256*256];
__device__ __align__(16) u16 g_P2l[256*256];

// pitches (bf16 units / bytes)
constexpr int PA1=216, PA1B=432;
constexpr int PBB =272;
constexpr int PA2=72,  PA2B=144;
constexpr int PZ =132;

// block kernel smem layout (bytes)
constexpr int A1HALF = 128*PA1*2;            // 55296
constexpr int OFF_A1H = 0;
constexpr int OFF_A1L = A1HALF;
constexpr int B1HALF = KRED*PBB;             // 56576
constexpr int OFF_B1H = 2*A1HALF;            // 110592
constexpr int OFF_B1L = OFF_B1H + B1HALF;
constexpr int SMEM_MMA = OFF_B1L + B1HALF;   // 223744
constexpr int OFF_ZBUF = 0;
constexpr int A2HALF = 192*PA2B;             // 27648
constexpr int OFF_A2H = 101376;
constexpr int OFF_A2L = OFF_A2H + A2HALF;
constexpr int B2HALF = 64*PBB;               // 17408
constexpr int OFF_B2H = OFF_A2L + A2HALF;
constexpr int OFF_B2L = OFF_B2H + B2HALF;
// post kernel smem layout
constexpr int OFF_XH = 0;                    // [128][136] u16
constexpr int OFF_XL = 34816;
constexpr int OFF_YH = 69632;                // [256][136] u16
constexpr int OFF_YL = 139264;
constexpr int SMEM_POST = 208896;

// ---------- helpers ----------
DI u16 f2bf(float x){ u16 u; asm("cvt.rn.bf16.f32 %0, %1;" : "=h"(u) : "f"(x)); return u; }
DI float bf2f(u16 u){ return __uint_as_float(((u32)u)<<16); }
DI u32 smem_u32(const void* p){ u32 a; asm("{ .reg .u64 t; cvta.to.shared.u64 t, %1; cvt.u32.u64 %0, t; }" : "=r"(a) : "l"(p)); return a; }
DI void ldm4(u32* r, u32 addr){
  asm volatile("ldmatrix.sync.aligned.m8n8.x4.shared.b16 {%0,%1,%2,%3},[%4];"
    : "=r"(r[0]),"=r"(r[1]),"=r"(r[2]),"=r"(r[3]) : "r"(addr));
}
DI void ldm4t(u32* r, u32 addr){
  asm volatile("ldmatrix.sync.aligned.m8n8.x4.trans.shared.b16 {%0,%1,%2,%3},[%4];"
    : "=r"(r[0]),"=r"(r[1]),"=r"(r[2]),"=r"(r[3]) : "r"(addr));
}
DI void mma16816(float* d, const u32* a, const u32* b){
  asm volatile("mma.sync.aligned.m16n8k16.row.col.f32.bf16.bf16.f32 "
    "{%0,%1,%2,%3},{%4,%5,%6,%7},{%8,%9},{%0,%1,%2,%3};"
    : "+f"(d[0]),"+f"(d[1]),"+f"(d[2]),"+f"(d[3])
    : "r"(a[0]),"r"(a[1]),"r"(a[2]),"r"(a[3]),"r"(b[0]),"r"(b[1]));
}
// direct-gmem A fragment load (m16n8k16 row-major canonical mapping)
DI void ldA_g(u32* a, const u16* base, int r0, int c0, int pitch, int lane){
  int r=r0+(lane>>2), c=c0+(lane&3)*2;
  const u16* p=base+r*pitch+c;
  a[0]=*(const u32*)(p);
  a[1]=*(const u32*)(p+8*pitch);
  a[2]=*(const u32*)(p+8);
  a[3]=*(const u32*)(p+8*pitch+8);
}

// ---------------- prep ----------------
__global__ void prep_kernel(const float* __restrict__ dw,const float* __restrict__ db,
    const float* __restrict__ cw,const float* __restrict__ cb,
    const float* __restrict__ sw,const float* __restrict__ rw,
    const float* __restrict__ p1w,const float* __restrict__ p2w){
  const int NA1=NB*128*PA1, NA2=NB*192*PA2;
  const int N2=NB*128, NP1=256*128, NP2=256*256;
  const int total=NA1+NA2+N2+NP1+NP2;
  for(int idx=blockIdx.x*blockDim.x+threadIdx.x;idx<total;idx+=gridDim.x*blockDim.x){
    int t=idx;
    if(t<NA1){
      int blk=t/(128*PA1); int rem=t%(128*PA1); int co=rem/PA1; int k=rem%PA1;
      float v=0.f;
      if(k<64)        v=dw[((blk*128+co)*64+k)*2+1];
      else if(k<128)  v=dw[((blk*128+co)*64+(k-64))*2+0];
      else if(k<KRED) v=cw[(blk*128+co)*80+(k-128)];
      u16 hi=f2bf(v), lo=f2bf(v-bf2f(hi));
      int base=blk*2*128*PA1;
      g_A1[base+co*PA1+k]=hi; g_A1[base+128*PA1+co*PA1+k]=lo;
      continue;
    }
    t-=NA1;
    if(t<NA2){
      int blk=t/(192*PA2); int rem=t%(192*PA2); int co=rem/PA2; int k=rem%PA2;
      float v=0.f;
      if(k<64) v=(co<128)?sw[(blk*128+co)*64+k]:rw[(blk*64+(co-128))*64+k];
      u16 hi=f2bf(v), lo=f2bf(v-bf2f(hi));
      int base=blk*2*192*PA2;
      g_A2[base+co*PA2+k]=hi; g_A2[base+192*PA2+co*PA2+k]=lo;
      continue;
    }
    t-=NA2;
    if(t<N2){ g_bz[t]=db[t]+cb[t]; continue; }
    t-=N2;
    if(t<NP1){
      float v=p1w[t];
      u16 hi=f2bf(v), lo=f2bf(v-bf2f(hi));
      g_P1h[t]=hi; g_P1l[t]=lo; continue;
    }
    t-=NP1;
    {
      float v=p2w[t];
      u16 hi=f2bf(v), lo=f2bf(v-bf2f(hi));
      g_P2h[t]=hi; g_P2l[t]=lo;
    }
  }
}

// ---------------- cond upsample ----------------
__global__ void cond_kernel(const float* __restrict__ mels,const float* __restrict__ mw,
    const float* __restrict__ mb){
  extern __shared__ float sm[];
  float* melS=sm;
  float* wS=sm+B*NM*128;
  const int tid=threadIdx.x;const int r=blockIdx.x;
  for(int k=tid;k<(B*NM*128)/4;k+=256)((float4*)melS)[k]=((const float4*)mels)[k];
  const int k1=255-r,k2=511-r;
  for(int idx=tid;idx<160*80;idx+=256){int j=idx/80,c=idx%80;
    int m=(j<80)?j:(j-80);int k=(j<80)?k1:k2;
    wS[idx]=mw[(c*NM+m)*512+k];}
  __syncthreads();
  for(int idx=tid;idx<B*NM*127;idx+=256){
    int q=idx%127;int c=(idx/127)%NM;int b=idx/(127*NM);
    float acc=mb[c];
    const float* m0=melS+b*NM*128+q;
    #pragma unroll 4
    for(int m=0;m<NM;m++){
      acc+=wS[m*80+c]*m0[m*128]+wS[(80+m)*80+c]*m0[m*128+1];}
    g_cond[(b*NM+c)*L+q*256+r]=acc;
  }
}

__global__ void init_res_kernel(const float* __restrict__ x,const float* __restrict__ iw,
    const float* __restrict__ ib){
  int idx=blockIdx.x*blockDim.x+threadIdx.x;
  if(idx>=B*R*L)return;
  int t=idx%L;int rc=(idx/L)%R;int b=idx/(L*R);
  g_res[0][idx]=iw[rc]*x[b*L+t]+ib[rc];
}

// ---------------- mma.sync WaveNet block (unchanged from R7) ----------------
__global__ void __launch_bounds__(512,1) mma_block_kernel(int blk,int d,int pp,int first,
    const float* __restrict__ skip_b,const float* __restrict__ res_b){
  extern __shared__ char smc[];
  const u32 sb=smem_u32(smc);
  const int tid=threadIdx.x;
  const int wid=tid>>5, lane=tid&31;
  const int bIdx=blockIdx.y;
  const int t0=blockIdx.x*TN;
  const float* res_in=g_res[pp]+bIdx*(R*L);
  float*       res_out=g_res[pp^1]+bIdx*(R*L);
  const float* condp=g_cond+bIdx*(NM*L);
  float*       skipp=g_skip+bIdx*(S*L);
  float* zbuf=(float*)(smc+OFF_ZBUF);

  const bool ad=((d&3)==0)&&(t0>=d);
  for(int k=tid;k<KRED*32;k+=512){
    int row=k>>5, c4=k&31;
    float4 v;
    if(row<64){ v=*(const float4*)(res_in+row*L+t0+c4*4); }
    else if(row<128){
      int ci=row-64;
      if(ad){ v=*(const float4*)(res_in+ci*L+t0-d+c4*4); }
      else{
        int tb=t0+c4*4-d;
        v.x=(tb  >=0)?res_in[ci*L+tb  ]:0.f;
        v.y=(tb+1>=0)?res_in[ci*L+tb+1]:0.f;
        v.z=(tb+2>=0)?res_in[ci*L+tb+2]:0.f;
        v.w=(tb+3>=0)?res_in[ci*L+tb+3]:0.f;
      }
    }else{ v=*(const float4*)(condp+(row-128)*L+t0+c4*4); }
    u16 h0=f2bf(v.x),h1=f2bf(v.y),h2=f2bf(v.z),h3=f2bf(v.w);
    u16 l0=f2bf(v.x-bf2f(h0)),l1=f2bf(v.y-bf2f(h1)),l2=f2bf(v.z-bf2f(h2)),l3=f2bf(v.w-bf2f(h3));
    u32 off=(u32)(row*PBB+c4*8);
    *(uint2*)(smc+OFF_B1H+off)=make_uint2((u32)h0|((u32)h1<<16),(u32)h2|((u32)h3<<16));
    *(uint2*)(smc+OFF_B1L+off)=make_uint2((u32)l0|((u32)l1<<16),(u32)l2|((u32)l3<<16));
  }
  {
    const uint4* src=(const uint4*)(g_A1+(size_t)blk*2*128*PA1);
    uint4* dst=(uint4*)(smc+OFF_A1H);
    #pragma unroll
    for(int i=0;i<14;i++){ int k=tid+i*512; if(k<6912) dst[k]=src[k]; }
  }
  __syncthreads();

  {
    const int cg=wid>>2, tg=wid&3;
    const int co0=cg*32, tw0=tg*32;
    float acc[2][4][4];
    #pragma unroll
    for(int m=0;m<2;m++)
      #pragma unroll
      for(int n=0;n<4;n++)
        #pragma unroll
        for(int q=0;q<4;q++) acc[m][n][q]=0.f;

    u32 aAH[2], aAL[2], bAH[2], bAL[2];
    #pragma unroll
    for(int m=0;m<2;m++){
      u32 ro=(u32)((co0+m*16+(lane&15))*PA1B+(lane>>4)*16);
      aAH[m]=sb+OFF_A1H+ro; aAL[m]=sb+OFF_A1L+ro;
    }
    #pragma unroll
    for(int s=0;s<2;s++){
      u32 ro=(u32)((lane&15)*PBB+(tw0+s*16+(lane>>4)*8)*2);
      bAH[s]=sb+OFF_B1H+ro; bAL[s]=sb+OFF_B1L+ro;
    }
    for(int ks=0;ks<13;ks++){
      u32 ah[2][4],al[2][4],bh[2][4],bl[2][4];
      #pragma unroll
      for(int m=0;m<2;m++){ ldm4(ah[m],aAH[m]+ks*32); ldm4(al[m],aAL[m]+ks*32); }
      #pragma unroll
      for(int s=0;s<2;s++){ ldm4t(bh[s],bAH[s]+ks*16*PBB); ldm4t(bl[s],bAL[s]+ks*16*PBB); }
      #pragma unroll
      for(int m=0;m<2;m++)
        #pragma unroll
        for(int n=0;n<4;n++){
          const u32* ph=&bh[n>>1][(n&1)*2];
          const u32* pl=&bl[n>>1][(n&1)*2];
          mma16816(acc[m][n], ah[m], ph);
          mma16816(acc[m][n], ah[m], pl);
          mma16816(acc[m][n], al[m], ph);
        }
    }
    __syncthreads();
    #pragma unroll
    for(int m=0;m<2;m++)
      #pragma unroll
      for(int n=0;n<4;n++){
        int co=co0+m*16+(lane>>2);
        int tt=tw0+n*8+(lane&3)*2;
        *(float2*)(zbuf+co*PZ+tt)      =make_float2(acc[m][n][0],acc[m][n][1]);
        *(float2*)(zbuf+(co+8)*PZ+tt)  =make_float2(acc[m][n][2],acc[m][n][3]);
      }
  }
  {
    const uint4* src=(const uint4*)(g_A2+(size_t)blk*2*192*PA2);
    uint4* dst=(uint4*)(smc+OFF_A2H);
    #pragma unroll
    for(int i=0;i<7;i++){ int k=tid+i*512; if(k<3456) dst[k]=src[k]; }
  }
  __syncthreads();

  {
    int ci=tid>>3, t16=(tid&7)*16;
    float bzf=g_bz[blk*128+ci], bzg=g_bz[blk*128+64+ci];
    u16 hh[16], hl[16];
    #pragma unroll
    for(int i=0;i<16;i++){
      float f=zbuf[ci*PZ+t16+i]+bzf;
      float g=zbuf[(64+ci)*PZ+t16+i]+bzg;
      float h=tanhf(f)*(1.0f/(1.0f+__expf(-g)));
      hh[i]=f2bf(h); hl[i]=f2bf(h-bf2f(hh[i]));
    }
    u32 off=(u32)(ci*PBB+t16*2);
    #pragma unroll
    for(int q=0;q<2;q++){
      *(uint4*)(smc+OFF_B2H+off+q*16)=make_uint4(
        (u32)hh[q*8+0]|((u32)hh[q*8+1]<<16),(u32)hh[q*8+2]|((u32)hh[q*8+3]<<16),
        (u32)hh[q*8+4]|((u32)hh[q*8+5]<<16),(u32)hh[q*8+6]|((u32)hh[q*8+7]<<16));
      *(uint4*)(smc+OFF_B2L+off+q*16)=make_uint4(
        (u32)hl[q*8+0]|((u32)hl[q*8+1]<<16),(u32)hl[q*8+2]|((u32)hl[q*8+3]<<16),
        (u32)hl[q*8+4]|((u32)hl[q*8+5]<<16),(u32)hl[q*8+6]|((u32)hl[q*8+7]<<16));
    }
  }
  __syncthreads();

  for(int tp=0;tp<2;tp++){
    int tau=wid+tp*16;
    if(tau<24){
      int cg=tau>>2, tg=tau&3;
      int co0=cg*32, tw0=tg*32;
      float acc[2][4][4];
      #pragma unroll
      for(int m=0;m<2;m++)
        #pragma unroll
        for(int n=0;n<4;n++)
          #pragma unroll
          for(int q=0;q<4;q++) acc[m][n][q]=0.f;
      u32 aAH[2],aAL[2],bAH[2],bAL[2];
      #pragma unroll
      for(int m=0;m<2;m++){
        u32 ro=(u32)((co0+m*16+(lane&15))*PA2B+(lane>>4)*16);
        aAH[m]=sb+OFF_A2H+ro; aAL[m]=sb+OFF_A2L+ro;
      }
      #pragma unroll
      for(int s=0;s<2;s++){
        u32 ro=(u32)((lane&15)*PBB+(tw0+s*16+(lane>>4)*8)*2);
        bAH[s]=sb+OFF_B2H+ro; bAL[s]=sb+OFF_B2L+ro;
      }
      #pragma unroll
      for(int ks=0;ks<4;ks++){
        u32 ah[2][4],al[2][4],bh[2][4],bl[2][4];
        #pragma unroll
        for(int m=0;m<2;m++){ ldm4(ah[m],aAH[m]+ks*32); ldm4(al[m],aAL[m]+ks*32); }
        #pragma unroll
        for(int s=0;s<2;s++){ ldm4t(bh[s],bAH[s]+ks*16*PBB); ldm4t(bl[s],bAL[s]+ks*16*PBB); }
        #pragma unroll
        for(int m=0;m<2;m++)
          #pragma unroll
          for(int n=0;n<4;n++){
            const u32* ph=&bh[n>>1][(n&1)*2];
            const u32* pl=&bl[n>>1][(n&1)*2];
            mma16816(acc[m][n], ah[m], ph);
            mma16816(acc[m][n], ah[m], pl);
            mma16816(acc[m][n], al[m], ph);
          }
      }
      #pragma unroll
      for(int m=0;m<2;m++)
        #pragma unroll
        for(int n=0;n<4;n++){
          int co=co0+m*16+(lane>>2);
          int tt=tw0+n*8+(lane&3)*2;
          *(float2*)(zbuf+co*PZ+tt)    =make_float2(acc[m][n][0],acc[m][n][1]);
          *(float2*)(zbuf+(co+8)*PZ+tt)=make_float2(acc[m][n][2],acc[m][n][3]);
        }
    }
  }
  __syncthreads();

  #pragma unroll
  for(int i=0;i<8;i++){
    int k=tid+i*512;
    int co=k>>5, c4=k&31; int tt=c4*4;
    float sb0=skip_b[blk*S+co];
    float4 v=make_float4(zbuf[co*PZ+tt]+sb0, zbuf[co*PZ+tt+1]+sb0,
                         zbuf[co*PZ+tt+2]+sb0, zbuf[co*PZ+tt+3]+sb0);
    float4* dst=(float4*)(skipp+co*L+t0+tt);
    if(!first){ float4 o=*dst; v.x+=o.x;v.y+=o.y;v.z+=o.z;v.w+=o.w; }
    *dst=v;
  }
  #pragma unroll
  for(int i=0;i<4;i++){
    int k=tid+i*512;
    int co=k>>5, c4=k&31; int tt=c4*4;
    float rb=res_b[blk*R+co];
    const float* zr=zbuf+(128+co)*PZ+tt;
    float4 cur=*(const float4*)(res_in+co*L+t0+tt);
    float4 v=make_float4(cur.x+zr[0]+rb,cur.y+zr[1]+rb,cur.z+zr[2]+rb,cur.w+zr[3]+rb);
    *(float4*)(res_out+co*L+t0+tt)=v;
  }
}

// ---------------- mma.sync post network ----------------
__global__ void __launch_bounds__(512,1) post_kernel(const float* __restrict__ p1b,
    const float* __restrict__ p2b,float* __restrict__ out){
  extern __shared__ char smc[];
  const u32 sb=smem_u32(smc);
  const int tid=threadIdx.x;
  const int wid=tid>>5, lane=tid&31;
  const int bIdx=blockIdx.y;
  const int t0=blockIdx.x*TT;

  // ---- stage x = relu(skip) as bf16 h/l [128k][136] ----
  for(int k=tid;k<S*32;k+=512){
    int row=k>>5, c4=k&31;
    float4 v=*(const float4*)(g_skip+(bIdx*S+row)*L+t0+c4*4);
    v.x=fmaxf(v.x,0.f);v.y=fmaxf(v.y,0.f);v.z=fmaxf(v.z,0.f);v.w=fmaxf(v.w,0.f);
    u16 h0=f2bf(v.x),h1=f2bf(v.y),h2=f2bf(v.z),h3=f2bf(v.w);
    u16 l0=f2bf(v.x-bf2f(h0)),l1=f2bf(v.y-bf2f(h1)),l2=f2bf(v.z-bf2f(h2)),l3=f2bf(v.w-bf2f(h3));
    u32 off=(u32)(row*PBB+c4*8);
    *(uint2*)(smc+OFF_XH+off)=make_uint2((u32)h0|((u32)h1<<16),(u32)h2|((u32)h3<<16));
    *(uint2*)(smc+OFF_XL+off)=make_uint2((u32)l0|((u32)l1<<16),(u32)l2|((u32)l3<<16));
  }
  __syncthreads();

  // ---- GEMM1: y1 = relu(W1 @ x + b1), M=256, K=128, 32 tiles / 2 rounds ----
  #pragma unroll
  for(int r=0;r<2;r++){
    int id=wid+r*16;
    int cg=id>>2, tg=id&3;
    int co0=cg*32, tw0=tg*32;
    float acc[2][4][4];
    #pragma unroll
    for(int m=0;m<2;m++)
      #pragma unroll
      for(int n=0;n<4;n++)
        #pragma unroll
        for(int q=0;q<4;q++) acc[m][n][q]=0.f;
    u32 bAH[2],bAL[2];
    #pragma unroll
    for(int s=0;s<2;s++){
      u32 ro=(u32)((lane&15)*PBB+(tw0+s*16+(lane>>4)*8)*2);
      bAH[s]=sb+OFF_XH+ro; bAL[s]=sb+OFF_XL+ro;
    }
    #pragma unroll
    for(int ks=0;ks<8;ks++){
      u32 ah[2][4],al[2][4],bh[2][4],bl[2][4];
      #pragma unroll
      for(int m=0;m<2;m++){
        ldA_g(ah[m], g_P1h, co0+m*16, ks*16, 128, lane);
        ldA_g(al[m], g_P1l, co0+m*16, ks*16, 128, lane);
      }
      #pragma unroll
      for(int s=0;s<2;s++){ ldm4t(bh[s],bAH[s]+ks*16*PBB); ldm4t(bl[s],bAL[s]+ks*16*PBB); }
      #pragma unroll
      for(int m=0;m<2;m++)
        #pragma unroll
        for(int n=0;n<4;n++){
          const u32* ph=&bh[n>>1][(n&1)*2];
          const u32* pl=&bl[n>>1][(n&1)*2];
          mma16816(acc[m][n], ah[m], ph);
          mma16816(acc[m][n], ah[m], pl);
          mma16816(acc[m][n], al[m], ph);
        }
    }
    // epilogue: bias+relu -> split -> y1S
    #pragma unroll
    for(int m=0;m<2;m++){
      int r0=co0+m*16+(lane>>2);
      float b0=p1b[r0], b1=p1b[r0+8];
      #pragma unroll
      for(int n=0;n<4;n++){
        int tt=tw0+n*8+(lane&3)*2;
        float y0=fmaxf(acc[m][n][0]+b0,0.f), y1=fmaxf(acc[m][n][1]+b0,0.f);
        float y2=fmaxf(acc[m][n][2]+b1,0.f), y3=fmaxf(acc[m][n][3]+b1,0.f);
        u16 h0=f2bf(y0),h1=f2bf(y1),h2=f2bf(y2),h3=f2bf(y3);
        u16 l0=f2bf(y0-bf2f(h0)),l1=f2bf(y1-bf2f(h1)),l2=f2bf(y2-bf2f(h2)),l3=f2bf(y3-bf2f(h3));
        *(u32*)(smc+OFF_YH+r0*PBB+tt*2)    =(u32)h0|((u32)h1<<16);
        *(u32*)(smc+OFF_YL+r0*PBB+tt*2)    =(u32)l0|((u32)l1<<16);
        *(u32*)(smc+OFF_YH+(r0+8)*PBB+tt*2)=(u32)h2|((u32)h3<<16);
        *(u32*)(smc+OFF_YL+(r0+8)*PBB+tt*2)=(u32)l2|((u32)l3<<16);
      }
    }
  }
  __syncthreads();

  // ---- GEMM2: out = W2 @ y1 + b2, M=256, K=256, 32 tiles / 2 rounds ----
  #pragma unroll
  for(int r=0;r<2;r++){
    int id=wid+r*16;
    int cg=id>>2, tg=id&3;
    int co0=cg*32, tw0=tg*32;
    float acc[2][4][4];
    #pragma unroll
    for(int m=0;m<2;m++)
      #pragma unroll
      for(int n=0;n<4;n++)
        #pragma unroll
        for(int q=0;q<4;q++) acc[m][n][q]=0.f;
    u32 bAH[2],bAL[2];
    #pragma unroll
    for(int s=0;s<2;s++){
      u32 ro=(u32)((lane&15)*PBB+(tw0+s*16+(lane>>4)*8)*2);
      bAH[s]=sb+OFF_YH+ro; bAL[s]=sb+OFF_YL+ro;
    }
    #pragma unroll
    for(int ks=0;ks<16;ks++){
      u32 ah[2][4],al[2][4],bh[2][4],bl[2][4];
      #pragma unroll
      for(int m=0;m<2;m++){
        ldA_g(ah[m], g_P2h, co0+m*16, ks*16, 256, lane);
        ldA_g(al[m], g_P2l, co0+m*16, ks*16, 256, lane);
      }
      #pragma unroll
      for(int s=0;s<2;s++){ ldm4t(bh[s],bAH[s]+ks*16*PBB); ldm4t(bl[s],bAL[s]+ks*16*PBB); }
      #pragma unroll
      for(int m=0;m<2;m++)
        #pragma unroll
        for(int n=0;n<4;n++){
          const u32* ph=&bh[n>>1][(n&1)*2];
          const u32* pl=&bl[n>>1][(n&1)*2];
          mma16816(acc[m][n], ah[m], ph);
          mma16816(acc[m][n], ah[m], pl);
          mma16816(acc[m][n], al[m], ph);
        }
    }
    // epilogue: bias -> gmem out
    #pragma unroll
    for(int m=0;m<2;m++){
      int r0=co0+m*16+(lane>>2);
      float b0=p2b[r0], b1=p2b[r0+8];
      #pragma unroll
      for(int n=0;n<4;n++){
        int tt=tw0+n*8+(lane&3)*2;
        *(float2*)(out+(bIdx*NC+r0)*L+t0+tt)  =make_float2(acc[m][n][0]+b0,acc[m][n][1]+b0);
        *(float2*)(out+(bIdx*NC+r0+8)*L+t0+tt)=make_float2(acc[m][n][2]+b1,acc[m][n][3]+b1);
      }
    }
  }
}

extern "C" void kernel_launch(void* const* d_in, const int* in_sizes, int n_in,
                              void* d_out, int out_size) {
  const float* x      =(const float*)d_in[0];
  const float* mels   =(const float*)d_in[1];
  const float* input_w=(const float*)d_in[2];
  const float* input_b=(const float*)d_in[3];
  const float* mel_w  =(const float*)d_in[4];
  const float* mel_b  =(const float*)d_in[5];
  const float* dil_w  =(const float*)d_in[6];
  const float* dil_b  =(const float*)d_in[7];
  const float* cond_w =(const float*)d_in[8];
  const float* cond_b =(const float*)d_in[9];
  const float* skip_w =(const float*)d_in[10];
  const float* skip_b =(const float*)d_in[11];
  const float* res_w  =(const float*)d_in[12];
  const float* res_b  =(const float*)d_in[13];
  const float* p1w    =(const float*)d_in[14];
  const float* p1b    =(const float*)d_in[15];
  const float* p2w    =(const float*)d_in[16];
  const float* p2b    =(const float*)d_in[17];
  float* out=(float*)d_out;

  const int condSmem=(B*NM*128+160*80)*4;
  cudaFuncSetAttribute(cond_kernel, cudaFuncAttributeMaxDynamicSharedMemorySize, condSmem);
  cudaFuncSetAttribute(mma_block_kernel, cudaFuncAttributeMaxDynamicSharedMemorySize, SMEM_MMA);
  cudaFuncSetAttribute(post_kernel, cudaFuncAttributeMaxDynamicSharedMemorySize, SMEM_POST);

  prep_kernel<<<1024,256>>>(dil_w,dil_b,cond_w,cond_b,skip_w,res_w,p1w,p2w);
  cond_kernel<<<256,256,condSmem>>>(mels,mel_w,mel_b);
  init_res_kernel<<<(B*R*L+255)/256,256>>>(x,input_w,input_b);
  for(int i=0;i<NB;i++){
    int d=1<<(i%MD);
    mma_block_kernel<<<dim3(NT2,B),512,SMEM_MMA>>>(i,d,i&1,i==0?1:0,skip_b,res_b);
  }
  post_kernel<<<dim3(NTILE,B),512,SMEM_POST>>>(p1b,p2b,out);
}